// round 12
// baseline (speedup 1.0000x reference)
#include <cuda_runtime.h>
#include <cuda_bf16.h>
#include <cstdint>

#define Nn 100000
#define Ee 600000

// ---------------- scratch (allocation-free: __device__ globals) --------------
__device__ float g_agg[Nn * 128];
__device__ float g_h[Nn * 128];
__device__ __align__(16) __nv_bfloat16 g_wb[6][2][128 * 136];
__device__ __align__(16) __nv_bfloat16 g_web[2][2][128 * 40];

// ---------------- helpers -----------------------------------------------------
__device__ __forceinline__ void red_add_v4(float* p, float4 v) {
    asm volatile("red.global.add.v4.f32 [%0], {%1, %2, %3, %4};"
                 :: "l"(p), "f"(v.x), "f"(v.y), "f"(v.z), "f"(v.w)
                 : "memory");
}
__device__ __forceinline__ uint32_t smem_u32(const void* p) {
    return (uint32_t)__cvta_generic_to_shared(p);
}
__device__ __forceinline__ void cp_async16(uint32_t dst, const void* src) {
    asm volatile("cp.async.cg.shared.global [%0], [%1], 16;"
                 :: "r"(dst), "l"(src));
}
__device__ __forceinline__ void cp_commit() {
    asm volatile("cp.async.commit_group;");
}
__device__ __forceinline__ void cp_wait0() {
    asm volatile("cp.async.wait_group 0;" ::: "memory");
}
__device__ __forceinline__ void cp_wait1() {
    asm volatile("cp.async.wait_group 1;" ::: "memory");
}
__device__ __forceinline__ void ldx4(uint32_t* r, uint32_t addr) {
    asm volatile("ldmatrix.sync.aligned.m8n8.x4.shared.b16 {%0, %1, %2, %3}, [%4];"
                 : "=r"(r[0]), "=r"(r[1]), "=r"(r[2]), "=r"(r[3]) : "r"(addr));
}
__device__ __forceinline__ void mma_bf16(float* c, const uint32_t* a,
                                         const uint32_t* b) {
    asm volatile("mma.sync.aligned.m16n8k16.row.col.f32.bf16.bf16.f32 "
                 "{%0, %1, %2, %3}, {%4, %5, %6, %7}, {%8, %9}, {%0, %1, %2, %3};"
                 : "+f"(c[0]), "+f"(c[1]), "+f"(c[2]), "+f"(c[3])
                 : "r"(a[0]), "r"(a[1]), "r"(a[2]), "r"(a[3]),
                   "r"(b[0]), "r"(b[1]));
}
__device__ __forceinline__ uint32_t bf2_u32(__nv_bfloat162 x) {
    uint32_t r;
    memcpy(&r, &x, 4);
    return r;
}
__device__ __forceinline__ uint32_t split_hi2(float a, float b, uint32_t& lo) {
    __nv_bfloat162 h = __floats2bfloat162_rn(a, b);
    __nv_bfloat162 l = __floats2bfloat162_rn(a - __bfloat162float(h.x),
                                             b - __bfloat162float(h.y));
    lo = bf2_u32(l);
    return bf2_u32(h);
}
// ---- bulk copy + mbarrier ----
__device__ __forceinline__ void mbar_init(uint32_t mb, uint32_t cnt) {
    asm volatile("mbarrier.init.shared.b64 [%0], %1;" :: "r"(mb), "r"(cnt) : "memory");
}
__device__ __forceinline__ void mbar_expect(uint32_t mb, uint32_t bytes) {
    asm volatile("mbarrier.arrive.expect_tx.shared.b64 _, [%0], %1;"
                 :: "r"(mb), "r"(bytes) : "memory");
}
__device__ __forceinline__ void bulk_ld(uint32_t dst, const void* src,
                                        uint32_t bytes, uint32_t mb) {
    asm volatile("cp.async.bulk.shared::cta.global.mbarrier::complete_tx::bytes "
                 "[%0], [%1], %2, [%3];"
                 :: "r"(dst), "l"(src), "r"(bytes), "r"(mb) : "memory");
}
__device__ __forceinline__ void mbar_wait(uint32_t mb, uint32_t parity) {
    uint32_t done;
    asm volatile("{\n\t.reg .pred p;\n\t"
                 "mbarrier.try_wait.parity.acquire.cta.shared::cta.b64 p, [%1], %2;\n\t"
                 "selp.b32 %0, 1, 0, p;\n\t}"
                 : "=r"(done) : "r"(mb), "r"(parity) : "memory");
    if (!done) {
        asm volatile("{\n\t.reg .pred P1;\n\t"
                     "WL_%=:\n\t"
                     "mbarrier.try_wait.parity.acquire.cta.shared::cta.b64 P1, [%0], %1, 0x989680;\n\t"
                     "@P1 bra.uni WD_%=;\n\t"
                     "bra.uni WL_%=;\n\t"
                     "WD_%=:\n\t}"
                     :: "r"(mb), "r"(parity) : "memory");
    }
}

// ---------------- init copy ---------------------------------------------------
__global__ void __launch_bounds__(256) copy_kernel(float4* __restrict__ dst,
                                                   const float4* __restrict__ src,
                                                   int n4) {
    int i = blockIdx.x * blockDim.x + threadIdx.x;
    if (i < n4) dst[i] = src[i];
}

// ---------------- fused weight prep (one launch) -------------------------------
__global__ void __launch_bounds__(256)
prep_all(const float* __restrict__ W1a, const float* __restrict__ W1b,
         const float* __restrict__ W2a, const float* __restrict__ W2b,
         const float* __restrict__ Wfc1, const float* __restrict__ Wfc2,
         const float* __restrict__ We1, const float* __restrict__ We2,
         __nv_bfloat16* __restrict__ wb, __nv_bfloat16* __restrict__ web) {
    int id = blockIdx.x * 256 + threadIdx.x;
    if (id < 81920) {
        int m = id / 16384, e = id % 16384;
        const float* W = (m == 0) ? W1a : (m == 1) ? W1b
                       : (m == 2) ? W2a : (m == 3) ? W2b : Wfc1;
        int n = e >> 7, k = e & 127;
        float v = W[k * 128 + n];
        __nv_bfloat16 h = __float2bfloat16_rn(v);
        __nv_bfloat16 l = __float2bfloat16_rn(v - __bfloat162float(h));
        wb[(size_t)m * 2 * 128 * 136 + n * 136 + k] = h;
        wb[((size_t)m * 2 + 1) * 128 * 136 + n * 136 + k] = l;
    } else if (id < 90112) {
        int e = id - 81920;
        int n = e >> 7, k = e & 127;
        float v = Wfc2[k * 64 + n];
        __nv_bfloat16 h = __float2bfloat16_rn(v);
        __nv_bfloat16 l = __float2bfloat16_rn(v - __bfloat162float(h));
        wb[(size_t)5 * 2 * 128 * 136 + n * 136 + k] = h;
        wb[((size_t)5 * 2 + 1) * 128 * 136 + n * 136 + k] = l;
    } else if (id < 98304) {
        int e = id - 90112;
        int m = e >> 12; e &= 4095;
        int n = e >> 5, k = e & 31;
        const float* We = m ? We2 : We1;
        float v = We[k * 128 + n];
        __nv_bfloat16 h = __float2bfloat16_rn(v);
        __nv_bfloat16 l = __float2bfloat16_rn(v - __bfloat162float(h));
        web[(size_t)m * 2 * 128 * 40 + n * 40 + k] = h;
        web[((size_t)m * 2 + 1) * 128 * 40 + n * 40 + k] = l;
    }
}

// ---------------- HMMA fused edge kernel (x-row prefetch into smem) ------------
// Dynamic smem (107520 B):
//   [0,10240) We-hi  [10240,20480) We-lo  [20480,30720) ef-hi  [30720,40960) ef-lo
//   [40960,106496) sX: 128 edges x 512B (prefetched x[src] rows)
//   [106496) sbias[128]  [107008) sdst[128]
__global__ void __launch_bounds__(256, 2)
edge_kernel(const float* __restrict__ xin,
            const int* __restrict__ src, const int* __restrict__ dst,
            const float* __restrict__ ef,
            const __nv_bfloat16* __restrict__ Weh,
            const __nv_bfloat16* __restrict__ Wel,
            const float* __restrict__ be,
            float* __restrict__ agg) {
    extern __shared__ char sm[];
    const uint32_t s0   = smem_u32(sm);
    const uint32_t sWeh = s0, sWel = s0 + 10240;
    const uint32_t sEfh = s0 + 20480, sEfl = s0 + 30720;
    const uint32_t sX   = s0 + 40960;
    float* sbias = (float*)(sm + 106496);
    int*   sdst  = (int*)(sm + 107008);

    const int tid  = threadIdx.x;
    const int wid  = tid >> 5;
    const int lane = tid & 31;
    const int base = blockIdx.x * 128;
    const int nvalid = min(128, Ee - base);

    // group A: We tiles
    for (int i = tid; i < 640; i += 256) {
        cp_async16(sWeh + i * 16, (const char*)Weh + i * 16);
        cp_async16(sWel + i * 16, (const char*)Wel + i * 16);
    }
    cp_commit();

    // group B: x[src] rows (thread t owns half-row of edge t/2)
    {
        const int e = tid >> 1, hf = tid & 1;
        int ge = min(base + e, Ee - 1);
        int s = __ldg(&src[ge]);
        const char* xr = (const char*)(xin + (size_t)s * 128) + hf * 256;
        const uint32_t dX = sX + e * 512 + hf * 256;
#pragma unroll
        for (int i = 0; i < 16; i++) cp_async16(dX + i * 16, xr + i * 16);
    }
    cp_commit();

    if (tid < 128) {
        sbias[tid] = be[tid];
        sdst[tid] = dst[min(base + tid, Ee - 1)];
    }

    // ef tile: sequential load, fp32 -> bf16 hi/lo, pitch 40
    {
        const int edge = tid >> 1, half = tid & 1;
        int ge = min(base + edge, Ee - 1);
        const float4* ap = (const float4*)(ef + (size_t)ge * 32 + half * 16);
        const uint32_t dh = sEfh + edge * 80 + half * 32;
        const uint32_t dl = sEfl + edge * 80 + half * 32;
#pragma unroll
        for (int i = 0; i < 4; i++) {
            float4 v = ap[i];
            uint32_t l0, l1;
            uint32_t h0 = split_hi2(v.x, v.y, l0);
            uint32_t h1 = split_hi2(v.z, v.w, l1);
            asm volatile("st.shared.v2.b32 [%0], {%1, %2};"
                         :: "r"(dh + i * 8), "r"(h0), "r"(h1));
            asm volatile("st.shared.v2.b32 [%0], {%1, %2};"
                         :: "r"(dl + i * 8), "r"(l0), "r"(l1));
        }
    }
    cp_wait1();               // We done (x rows may still be in flight)
    __syncthreads();

    const int g = lane >> 2, tq = lane & 3;
    const uint32_t aoff = sEfh
        + (uint32_t)(wid * 16 + (lane & 15)) * 80 + ((lane >> 4) ? 16 : 0);
    const uint32_t aloff = aoff + (sEfl - sEfh);
    const int brow = (lane & 7) + ((lane >> 4) << 3);
    const uint32_t boff = sWeh + (uint32_t)brow * 80 + ((lane & 8) ? 16 : 0);
    const uint32_t bloff = boff + (sWel - sWeh);

    float acc[16][4];
#pragma unroll
    for (int ni = 0; ni < 16; ni++) {
        float2 b = *(const float2*)(sbias + ni * 8 + tq * 2);
        acc[ni][0] = b.x; acc[ni][1] = b.y;
        acc[ni][2] = b.x; acc[ni][3] = b.y;
    }

#pragma unroll
    for (int ks = 0; ks < 2; ks++) {
        uint32_t ah[4], al[4];
        ldx4(ah, aoff + ks * 32);
        ldx4(al, aloff + ks * 32);
#pragma unroll
        for (int np = 0; np < 8; np++) {
            uint32_t rh[4], rl[4];
            ldx4(rh, boff + np * (16 * 80) + ks * 32);
            ldx4(rl, bloff + np * (16 * 80) + ks * 32);
            uint32_t bh0[2] = {rh[0], rh[1]}, bh1[2] = {rh[2], rh[3]};
            uint32_t bl0[2] = {rl[0], rl[1]}, bl1[2] = {rl[2], rl[3]};
            mma_bf16(acc[np * 2],     ah, bh0);
            mma_bf16(acc[np * 2],     ah, bl0);
            mma_bf16(acc[np * 2],     al, bh0);
            mma_bf16(acc[np * 2 + 1], ah, bh1);
            mma_bf16(acc[np * 2 + 1], ah, bl1);
            mma_bf16(acc[np * 2 + 1], al, bh1);
        }
    }

    // lane-pair merge -> float4 ownership (R11)
    const bool evn = ((lane & 1) == 0);
    float4 rowA[8], rowB[8];
#pragma unroll
    for (int i = 0; i < 8; i++) {
        float s0v = evn ? acc[i + 8][0] : acc[i][0];
        float s1v = evn ? acc[i + 8][1] : acc[i][1];
        float s2v = evn ? acc[i + 8][2] : acc[i][2];
        float s3v = evn ? acc[i + 8][3] : acc[i][3];
        float g0 = __shfl_xor_sync(0xffffffffu, s0v, 1);
        float g1 = __shfl_xor_sync(0xffffffffu, s1v, 1);
        float g2 = __shfl_xor_sync(0xffffffffu, s2v, 1);
        float g3 = __shfl_xor_sync(0xffffffffu, s3v, 1);
        float k0 = evn ? acc[i][0] : acc[i + 8][0];
        float k1 = evn ? acc[i][1] : acc[i + 8][1];
        float k2 = evn ? acc[i][2] : acc[i + 8][2];
        float k3 = evn ? acc[i][3] : acc[i + 8][3];
        rowA[i] = evn ? make_float4(k0, k1, g0, g1) : make_float4(g0, g1, k0, k1);
        rowB[i] = evn ? make_float4(k2, k3, g2, g3) : make_float4(g2, g3, k2, k3);
    }
    const int nk0 = evn ? 0 : 8;
    const int jq  = (lane >> 1) & 1;

    cp_wait0();               // x rows resident
    __syncthreads();

    // epilogue: x from smem + red.add.v4 scatter
    const int er0 = wid * 16 + g;
#pragma unroll
    for (int half = 0; half < 2; half++) {
        const int er = er0 + half * 8;
        if (er < nvalid) {
            const size_t drow = (size_t)sdst[er] * 128;
            const uint32_t xrow = sX + (uint32_t)er * 512;
#pragma unroll
            for (int i = 0; i < 8; i++) {
                const int cb = (nk0 + i) * 8 + 4 * jq;
                float4 ev = half ? rowB[i] : rowA[i];
                float4 xv;
                asm volatile("ld.shared.v4.f32 {%0, %1, %2, %3}, [%4];"
                             : "=f"(xv.x), "=f"(xv.y), "=f"(xv.z), "=f"(xv.w)
                             : "r"(xrow + cb * 4));
                float4 m;
                m.x = fmaxf(xv.x + ev.x, 0.f);
                m.y = fmaxf(xv.y + ev.y, 0.f);
                m.z = fmaxf(xv.z + ev.z, 0.f);
                m.w = fmaxf(xv.w + ev.w, 0.f);
                red_add_v4(agg + drow + cb, m);
            }
        }
    }
}

// ---------------- shared GEMM pieces (unchanged from R11) ----------------------
template <int NF>
__device__ __forceinline__ void mma_stage(
    uint32_t sAh, uint32_t sAl, uint32_t sWh, uint32_t sWl,
    uint32_t aoff, int cw, int lane, const float* __restrict__ bias,
    float (&acc)[4][NF][4]) {
    const int tq = lane & 3;
    const int brow = (lane & 7) + ((lane >> 4) << 3);
    const uint32_t boff = (uint32_t)(cw * (8 * NF) + brow) * 272
                        + ((lane & 8) ? 16 : 0);
#pragma unroll
    for (int ni = 0; ni < NF; ni++) {
        float2 b = __ldg((const float2*)(bias + cw * (8 * NF) + ni * 8 + tq * 2));
#pragma unroll
        for (int mi = 0; mi < 4; mi++) {
            acc[mi][ni][0] = b.x; acc[mi][ni][1] = b.y;
            acc[mi][ni][2] = b.x; acc[mi][ni][3] = b.y;
        }
    }
#pragma unroll
    for (int ks = 0; ks < 8; ks++) {
        uint32_t ah[4][4], al[4][4], bh[NF][2], bl[NF][2];
#pragma unroll
        for (int mi = 0; mi < 4; mi++) {
            ldx4(ah[mi], sAh + aoff + mi * 4352 + ks * 32);
            ldx4(al[mi], sAl + aoff + mi * 4352 + ks * 32);
        }
#pragma unroll
        for (int np = 0; np < NF / 2; np++) {
            uint32_t r[4];
            ldx4(r, sWh + boff + np * 4352 + ks * 32);
            bh[np * 2][0] = r[0]; bh[np * 2][1] = r[1];
            bh[np * 2 + 1][0] = r[2]; bh[np * 2 + 1][1] = r[3];
            ldx4(r, sWl + boff + np * 4352 + ks * 32);
            bl[np * 2][0] = r[0]; bl[np * 2][1] = r[1];
            bl[np * 2 + 1][0] = r[2]; bl[np * 2 + 1][1] = r[3];
        }
#pragma unroll
        for (int mi = 0; mi < 4; mi++)
#pragma unroll
            for (int ni = 0; ni < NF; ni++) {
                mma_bf16(acc[mi][ni], ah[mi], bh[ni]);
                mma_bf16(acc[mi][ni], ah[mi], bl[ni]);
                mma_bf16(acc[mi][ni], al[mi], bh[ni]);
            }
    }
}

template <int ACT>
__device__ __forceinline__ void twrite(
    float (&acc)[4][4][4], uint32_t sAh, uint32_t sAl, int cw, int lane) {
    const int g = lane >> 2, tq = lane & 3;
#pragma unroll
    for (int mi = 0; mi < 4; mi++) {
        const int r0 = mi * 16 + g;
#pragma unroll
        for (int ni = 0; ni < 4; ni++) {
            const int col = cw * 32 + ni * 8 + tq * 2;
            float v0 = acc[mi][ni][0], v1 = acc[mi][ni][1];
            float v2 = acc[mi][ni][2], v3 = acc[mi][ni][3];
            if (ACT == 1) {
                v0 = fmaxf(v0, 0.f); v1 = fmaxf(v1, 0.f);
                v2 = fmaxf(v2, 0.f); v3 = fmaxf(v3, 0.f);
            } else {
                v0 = tanhf(v0); v1 = tanhf(v1);
                v2 = tanhf(v2); v3 = tanhf(v3);
            }
            uint32_t lo0, lo1;
            uint32_t hi0 = split_hi2(v0, v1, lo0);
            uint32_t hi1 = split_hi2(v2, v3, lo1);
            const uint32_t d0 = (uint32_t)r0 * 272 + col * 2;
            asm volatile("st.shared.b32 [%0], %1;" :: "r"(sAh + d0), "r"(hi0));
            asm volatile("st.shared.b32 [%0], %1;" :: "r"(sAl + d0), "r"(lo0));
            asm volatile("st.shared.b32 [%0], %1;" :: "r"(sAh + d0 + 8 * 272), "r"(hi1));
            asm volatile("st.shared.b32 [%0], %1;" :: "r"(sAl + d0 + 8 * 272), "r"(lo1));
        }
    }
}

__device__ __forceinline__ void aconvert(
    const float* __restrict__ A, int mbase, int nrows,
    uint32_t sAh, uint32_t sAl, int tid) {
    const int row = tid >> 1, half = tid & 1;
    int grow = min(mbase + row, nrows - 1);
    const float* ap = A + (size_t)grow * 128 + half * 64;
    const uint32_t d = row * 272 + half * 128;
#pragma unroll
    for (int i = 0; i < 8; i++) {
        float4 v0 = *(const float4*)(ap + i * 8);
        float4 v1 = *(const float4*)(ap + i * 8 + 4);
        uint32_t l0, l1, l2, l3;
        uint32_t h0 = split_hi2(v0.x, v0.y, l0);
        uint32_t h1 = split_hi2(v0.z, v0.w, l1);
        uint32_t h2 = split_hi2(v1.x, v1.y, l2);
        uint32_t h3 = split_hi2(v1.z, v1.w, l3);
        asm volatile("st.shared.v4.b32 [%0], {%1, %2, %3, %4};"
                     :: "r"(sAh + d + i * 16), "r"(h0), "r"(h1), "r"(h2), "r"(h3));
        asm volatile("st.shared.v4.b32 [%0], {%1, %2, %3, %4};"
                     :: "r"(sAl + d + i * 16), "r"(l0), "r"(l1), "r"(l2), "r"(l3));
    }
}

// ---------------- two-stage fused node GEMM ------------------------------------
template <int COUT2, int ACT1, int ACT2>
__global__ void __launch_bounds__(128, 2)
fgemm(const float* __restrict__ A,
      const __nv_bfloat16* __restrict__ W1, const __nv_bfloat16* __restrict__ W2,
      const float* __restrict__ b1, const float* __restrict__ b2,
      float* __restrict__ out, float* __restrict__ out2, int nrows, int ntiles) {
    constexpr int NW2 = COUT2 / 4;
    constexpr int NF2 = NW2 / 8;
    constexpr uint32_t AB  = 64 * 272;
    constexpr uint32_t WHB = 128 * 272;
    constexpr uint32_t WBYTES = 2 * WHB;

    extern __shared__ char sm[];
    const uint32_t s0  = smem_u32(sm);
    const uint32_t sAh = s0, sAl = s0 + AB;
    const uint32_t sWh = s0 + 2 * AB, sWl = sWh + WHB;
    __shared__ __align__(8) unsigned long long bw_store;
    const uint32_t bw = smem_u32(&bw_store);

    const int tid  = threadIdx.x;
    const int lane = tid & 31;
    const int cw   = tid >> 5;
    const int g = lane >> 2, tq = lane & 3;
    const uint32_t aoff = (uint32_t)(lane & 15) * 272 + ((lane >> 4) ? 16 : 0);

    if (tid == 0) mbar_init(bw, 1);
    __syncthreads();
    if (tid == 0) { mbar_expect(bw, WBYTES); bulk_ld(sWh, W1, WBYTES, bw); }

    int ph = 0;
    for (int mt = blockIdx.x; mt < ntiles; mt += gridDim.x) {
        const int mbase = mt * 64;
        aconvert(A, mbase, nrows, sAh, sAl, tid);
        __syncthreads();
        mbar_wait(bw, ph & 1); ph++;

        float acc[4][4][4];
        mma_stage<4>(sAh, sAl, sWh, sWl, aoff, cw, lane, b1, acc);
        __syncthreads();
        if (tid == 0) { mbar_expect(bw, WBYTES); bulk_ld(sWh, W2, WBYTES, bw); }
        twrite<ACT1>(acc, sAh, sAl, cw, lane);
        __syncthreads();
        mbar_wait(bw, ph & 1); ph++;

        float acc2[4][NF2][4];
        mma_stage<NF2>(sAh, sAl, sWh, sWl, aoff, cw, lane, b2, acc2);
        __syncthreads();
        if (tid == 0 && mt + gridDim.x < ntiles) {
            mbar_expect(bw, WBYTES); bulk_ld(sWh, W1, WBYTES, bw);
        }
#pragma unroll
        for (int mi = 0; mi < 4; mi++) {
            const int r0 = mbase + mi * 16 + g;
#pragma unroll
            for (int ni = 0; ni < NF2; ni++) {
                const int col = cw * NW2 + ni * 8 + tq * 2;
                float v0 = acc2[mi][ni][0], v1 = acc2[mi][ni][1];
                float v2 = acc2[mi][ni][2], v3 = acc2[mi][ni][3];
                if (ACT2 == 2) {
                    v0 = tanhf(v0); v1 = tanhf(v1);
                    v2 = tanhf(v2); v3 = tanhf(v3);
                }
                if (r0 < nrows) {
                    *(float2*)(out + (size_t)r0 * COUT2 + col) = make_float2(v0, v1);
                    if (out2)
                        *(float2*)(out2 + (size_t)r0 * COUT2 + col) = make_float2(v0, v1);
                }
                if (r0 + 8 < nrows) {
                    *(float2*)(out + (size_t)(r0 + 8) * COUT2 + col) = make_float2(v2, v3);
                    if (out2)
                        *(float2*)(out2 + (size_t)(r0 + 8) * COUT2 + col) = make_float2(v2, v3);
                }
            }
        }
    }
}

// ---------------- four-stage fused GEMM: layer2 MLP + head ---------------------
__global__ void __launch_bounds__(128, 2)
fgemm4(const float* __restrict__ A,
       const __nv_bfloat16* __restrict__ Wa, const __nv_bfloat16* __restrict__ Wb,
       const __nv_bfloat16* __restrict__ Wc, const __nv_bfloat16* __restrict__ Wd,
       const float* __restrict__ ba, const float* __restrict__ bb,
       const float* __restrict__ bc, const float* __restrict__ bd,
       float* __restrict__ out, int nrows, int ntiles) {
    constexpr uint32_t AB  = 64 * 272;
    constexpr uint32_t WHB = 128 * 272;
    constexpr uint32_t WBYTES = 2 * WHB;

    extern __shared__ char sm[];
    const uint32_t s0  = smem_u32(sm);
    const uint32_t sAh = s0, sAl = s0 + AB;
    const uint32_t sWh = s0 + 2 * AB, sWl = sWh + WHB;
    __shared__ __align__(8) unsigned long long bw_store;
    const uint32_t bw = smem_u32(&bw_store);

    const int tid  = threadIdx.x;
    const int lane = tid & 31;
    const int cw   = tid >> 5;
    const int g = lane >> 2, tq = lane & 3;
    const uint32_t aoff = (uint32_t)(lane & 15) * 272 + ((lane >> 4) ? 16 : 0);

    if (tid == 0) mbar_init(bw, 1);
    __syncthreads();
    if (tid == 0) { mbar_expect(bw, WBYTES); bulk_ld(sWh, Wa, WBYTES, bw); }

    int ph = 0;
    for (int mt = blockIdx.x; mt < ntiles; mt += gridDim.x) {
        const int mbase = mt * 64;
        aconvert(A, mbase, nrows, sAh, sAl, tid);
        __syncthreads();
        mbar_wait(bw, ph & 1); ph++;

        {
            float acc[4][4][4];
            mma_stage<4>(sAh, sAl, sWh, sWl, aoff, cw, lane, ba, acc);
            __syncthreads();
            if (tid == 0) { mbar_expect(bw, WBYTES); bulk_ld(sWh, Wb, WBYTES, bw); }
            twrite<1>(acc, sAh, sAl, cw, lane);
            __syncthreads();
            mbar_wait(bw, ph & 1); ph++;
        }
        {
            float acc[4][4][4];
            mma_stage<4>(sAh, sAl, sWh, sWl, aoff, cw, lane, bb, acc);
            __syncthreads();
            if (tid == 0) { mbar_expect(bw, WBYTES); bulk_ld(sWh, Wc, WBYTES, bw); }
            twrite<2>(acc, sAh, sAl, cw, lane);
            __syncthreads();
            mbar_wait(bw, ph & 1); ph++;
        }
        {
            float acc[4][4][4];
            mma_stage<4>(sAh, sAl, sWh, sWl, aoff, cw, lane, bc, acc);
            __syncthreads();
            if (tid == 0) { mbar_expect(bw, WBYTES); bulk_ld(sWh, Wd, WBYTES, bw); }
            twrite<2>(acc, sAh, sAl, cw, lane);
            __syncthreads();
            mbar_wait(bw, ph & 1); ph++;
        }
        {
            float acc[4][2][4];
            mma_stage<2>(sAh, sAl, sWh, sWl, aoff, cw, lane, bd, acc);
            __syncthreads();
            if (tid == 0 && mt + gridDim.x < ntiles) {
                mbar_expect(bw, WBYTES); bulk_ld(sWh, Wa, WBYTES, bw);
            }
#pragma unroll
            for (int mi = 0; mi < 4; mi++) {
                const int r0 = mbase + mi * 16 + g;
#pragma unroll
                for (int ni = 0; ni < 2; ni++) {
                    const int col = cw * 16 + ni * 8 + tq * 2;
                    if (r0 < nrows)
                        *(float2*)(out + (size_t)r0 * 64 + col)
                            = make_float2(acc[mi][ni][0], acc[mi][ni][1]);
                    if (r0 + 8 < nrows)
                        *(float2*)(out + (size_t)(r0 + 8) * 64 + col)
                            = make_float2(acc[mi][ni][2], acc[mi][ni][3]);
                }
            }
        }
    }
}

// ---------------- launch ------------------------------------------------------
extern "C" void kernel_launch(void* const* d_in, const int* in_sizes, int n_in,
                              void* d_out, int out_size) {
    const float* x    = (const float*)d_in[0];
    const int*   ei   = (const int*)d_in[1];
    const float* ef   = (const float*)d_in[2];
    const float* We1  = (const float*)d_in[3];
    const float* be1  = (const float*)d_in[4];
    const float* W1a  = (const float*)d_in[5];
    const float* b1a  = (const float*)d_in[6];
    const float* W1b  = (const float*)d_in[7];
    const float* b1b  = (const float*)d_in[8];
    const float* We2  = (const float*)d_in[9];
    const float* be2  = (const float*)d_in[10];
    const float* W2a  = (const float*)d_in[11];
    const float* b2a  = (const float*)d_in[12];
    const float* W2b  = (const float*)d_in[13];
    const float* b2b  = (const float*)d_in[14];
    const float* Wfc1 = (const float*)d_in[15];
    const float* bfc1 = (const float*)d_in[16];
    const float* Wfc2 = (const float*)d_in[17];
    const float* bfc2 = (const float*)d_in[18];
    float* out = (float*)d_out;

    float *agg, *h;
    __nv_bfloat16 *wb, *web;
    cudaGetSymbolAddress((void**)&agg, g_agg);
    cudaGetSymbolAddress((void**)&h,   g_h);
    cudaGetSymbolAddress((void**)&wb,  g_wb);
    cudaGetSymbolAddress((void**)&web, g_web);
    auto WB = [&](int m) { return wb + (size_t)m * 2 * 128 * 136; };
    auto WE = [&](int m, int s) { return web + ((size_t)m * 2 + s) * 128 * 40; };

    const int* srcp = ei;
    const int* dstp = ei + Ee;

    const int n4 = Nn * 128 / 4;
    const int cpG = (n4 + 255) / 256;
    const int egG = (Ee + 127) / 128;            // 4688
    const int ntiles = (Nn + 63) / 64;           // 1563
    const int gG = 296;

    constexpr int SME = 107520;
    constexpr int SMF = 2 * 17408 + 2 * 34816;   // 104448
    cudaFuncSetAttribute(edge_kernel, cudaFuncAttributeMaxDynamicSharedMemorySize, SME);
    cudaFuncSetAttribute(fgemm<128, 1, 2>, cudaFuncAttributeMaxDynamicSharedMemorySize, SMF);
    cudaFuncSetAttribute(fgemm4, cudaFuncAttributeMaxDynamicSharedMemorySize, SMF);

    prep_all<<<384, 256>>>(W1a, W1b, W2a, W2b, Wfc1, Wfc2, We1, We2, wb, web);

    // Layer 1: agg = x; agg += relu-msgs; h = tanh(relu(agg@W1a)@W1b); agg = h
    copy_kernel<<<cpG, 256>>>((float4*)agg, (const float4*)x, n4);
    edge_kernel<<<egG, 256, SME>>>(x, srcp, dstp, ef, WE(0, 0), WE(0, 1), be1, agg);
    fgemm<128, 1, 2><<<gG, 128, SMF>>>(agg, WB(0), WB(1), b1a, b1b, h, agg, Nn, ntiles);

    // Layer 2 + head (fused): agg(=h) += msgs(h);
    // out = tanh(tanh(relu(agg@W2a)@W2b)@Wfc1)@Wfc2
    edge_kernel<<<egG, 256, SME>>>(h, srcp, dstp, ef, WE(1, 0), WE(1, 1), be2, agg);
    fgemm4<<<gG, 128, SMF>>>(agg, WB(2), WB(3), WB(4), WB(5),
                             b2a, b2b, bfc1, bfc2, out, Nn, ntiles);
}

// round 13
// speedup vs baseline: 1.1735x; 1.1735x over previous
#include <cuda_runtime.h>
#include <cuda_bf16.h>
#include <cstdint>

#define Nn 100000
#define Ee 600000

// ---------------- scratch (allocation-free: __device__ globals) --------------
__device__ float g_agg[Nn * 128];
__device__ float g_h[Nn * 128];
__device__ __align__(16) __nv_bfloat16 g_wb[6][2][128 * 136];
__device__ __align__(16) __nv_bfloat16 g_web[2][2][128 * 40];
__device__ int g_tc[4];          // dynamic tile counters (zeroed by prep_all)

// ---------------- helpers -----------------------------------------------------
__device__ __forceinline__ void red_add_v4(float* p, float4 v) {
    asm volatile("red.global.add.v4.f32 [%0], {%1, %2, %3, %4};"
                 :: "l"(p), "f"(v.x), "f"(v.y), "f"(v.z), "f"(v.w)
                 : "memory");
}
__device__ __forceinline__ uint32_t smem_u32(const void* p) {
    return (uint32_t)__cvta_generic_to_shared(p);
}
__device__ __forceinline__ void cp_async16(uint32_t dst, const void* src) {
    asm volatile("cp.async.cg.shared.global [%0], [%1], 16;"
                 :: "r"(dst), "l"(src));
}
__device__ __forceinline__ void cp_commit() {
    asm volatile("cp.async.commit_group;");
}
__device__ __forceinline__ void cp_wait0() {
    asm volatile("cp.async.wait_group 0;" ::: "memory");
}
__device__ __forceinline__ void ldx4(uint32_t* r, uint32_t addr) {
    asm volatile("ldmatrix.sync.aligned.m8n8.x4.shared.b16 {%0, %1, %2, %3}, [%4];"
                 : "=r"(r[0]), "=r"(r[1]), "=r"(r[2]), "=r"(r[3]) : "r"(addr));
}
__device__ __forceinline__ void mma_bf16(float* c, const uint32_t* a,
                                         const uint32_t* b) {
    asm volatile("mma.sync.aligned.m16n8k16.row.col.f32.bf16.bf16.f32 "
                 "{%0, %1, %2, %3}, {%4, %5, %6, %7}, {%8, %9}, {%0, %1, %2, %3};"
                 : "+f"(c[0]), "+f"(c[1]), "+f"(c[2]), "+f"(c[3])
                 : "r"(a[0]), "r"(a[1]), "r"(a[2]), "r"(a[3]),
                   "r"(b[0]), "r"(b[1]));
}
__device__ __forceinline__ uint32_t bf2_u32(__nv_bfloat162 x) {
    uint32_t r;
    memcpy(&r, &x, 4);
    return r;
}
__device__ __forceinline__ uint32_t split_hi2(float a, float b, uint32_t& lo) {
    __nv_bfloat162 h = __floats2bfloat162_rn(a, b);
    __nv_bfloat162 l = __floats2bfloat162_rn(a - __bfloat162float(h.x),
                                             b - __bfloat162float(h.y));
    lo = bf2_u32(l);
    return bf2_u32(h);
}
// ---- bulk copy + mbarrier ----
__device__ __forceinline__ void mbar_init(uint32_t mb, uint32_t cnt) {
    asm volatile("mbarrier.init.shared.b64 [%0], %1;" :: "r"(mb), "r"(cnt) : "memory");
}
__device__ __forceinline__ void mbar_expect(uint32_t mb, uint32_t bytes) {
    asm volatile("mbarrier.arrive.expect_tx.shared.b64 _, [%0], %1;"
                 :: "r"(mb), "r"(bytes) : "memory");
}
__device__ __forceinline__ void bulk_ld(uint32_t dst, const void* src,
                                        uint32_t bytes, uint32_t mb) {
    asm volatile("cp.async.bulk.shared::cta.global.mbarrier::complete_tx::bytes "
                 "[%0], [%1], %2, [%3];"
                 :: "r"(dst), "l"(src), "r"(bytes), "r"(mb) : "memory");
}
__device__ __forceinline__ void mbar_wait(uint32_t mb, uint32_t parity) {
    uint32_t done;
    asm volatile("{\n\t.reg .pred p;\n\t"
                 "mbarrier.try_wait.parity.acquire.cta.shared::cta.b64 p, [%1], %2;\n\t"
                 "selp.b32 %0, 1, 0, p;\n\t}"
                 : "=r"(done) : "r"(mb), "r"(parity) : "memory");
    if (!done) {
        asm volatile("{\n\t.reg .pred P1;\n\t"
                     "WL_%=:\n\t"
                     "mbarrier.try_wait.parity.acquire.cta.shared::cta.b64 P1, [%0], %1, 0x989680;\n\t"
                     "@P1 bra.uni WD_%=;\n\t"
                     "bra.uni WL_%=;\n\t"
                     "WD_%=:\n\t}"
                     :: "r"(mb), "r"(parity) : "memory");
    }
}

// ---------------- init copy ---------------------------------------------------
__global__ void __launch_bounds__(256) copy_kernel(float4* __restrict__ dst,
                                                   const float4* __restrict__ src,
                                                   int n4) {
    int i = blockIdx.x * blockDim.x + threadIdx.x;
    if (i < n4) dst[i] = src[i];
}

// ---------------- fused weight prep (one launch; also zeroes tile counters) ----
__global__ void __launch_bounds__(256)
prep_all(const float* __restrict__ W1a, const float* __restrict__ W1b,
         const float* __restrict__ W2a, const float* __restrict__ W2b,
         const float* __restrict__ Wfc1, const float* __restrict__ Wfc2,
         const float* __restrict__ We1, const float* __restrict__ We2,
         __nv_bfloat16* __restrict__ wb, __nv_bfloat16* __restrict__ web,
         int* __restrict__ tc) {
    int id = blockIdx.x * 256 + threadIdx.x;
    if (id < 81920) {
        int m = id / 16384, e = id % 16384;
        const float* W = (m == 0) ? W1a : (m == 1) ? W1b
                       : (m == 2) ? W2a : (m == 3) ? W2b : Wfc1;
        int n = e >> 7, k = e & 127;
        float v = W[k * 128 + n];
        __nv_bfloat16 h = __float2bfloat16_rn(v);
        __nv_bfloat16 l = __float2bfloat16_rn(v - __bfloat162float(h));
        wb[(size_t)m * 2 * 128 * 136 + n * 136 + k] = h;
        wb[((size_t)m * 2 + 1) * 128 * 136 + n * 136 + k] = l;
    } else if (id < 90112) {
        int e = id - 81920;
        int n = e >> 7, k = e & 127;
        float v = Wfc2[k * 64 + n];
        __nv_bfloat16 h = __float2bfloat16_rn(v);
        __nv_bfloat16 l = __float2bfloat16_rn(v - __bfloat162float(h));
        wb[(size_t)5 * 2 * 128 * 136 + n * 136 + k] = h;
        wb[((size_t)5 * 2 + 1) * 128 * 136 + n * 136 + k] = l;
    } else if (id < 98304) {
        int e = id - 90112;
        int m = e >> 12; e &= 4095;
        int n = e >> 5, k = e & 31;
        const float* We = m ? We2 : We1;
        float v = We[k * 128 + n];
        __nv_bfloat16 h = __float2bfloat16_rn(v);
        __nv_bfloat16 l = __float2bfloat16_rn(v - __bfloat162float(h));
        web[(size_t)m * 2 * 128 * 40 + n * 40 + k] = h;
        web[((size_t)m * 2 + 1) * 128 * 40 + n * 40 + k] = l;
    } else if (id < 98308) {
        tc[id - 98304] = 0;
    }
}

// ---------------- HMMA fused edge kernel (R11 exact — best known) --------------
__global__ void __launch_bounds__(256, 2)
edge_kernel(const float* __restrict__ xin,
            const int* __restrict__ src, const int* __restrict__ dst,
            const float* __restrict__ ef,
            const __nv_bfloat16* __restrict__ Weh,
            const __nv_bfloat16* __restrict__ Wel,
            const float* __restrict__ be,
            float* __restrict__ agg) {
    __shared__ __align__(16) __nv_bfloat16 sWeh[128 * 40], sWel[128 * 40];
    __shared__ __align__(16) __nv_bfloat16 sEfh[128 * 40], sEfl[128 * 40];
    __shared__ float sbias[128];
    __shared__ int ssrc[128], sdst[128];

    const int tid  = threadIdx.x;
    const int wid  = tid >> 5;
    const int lane = tid & 31;
    const int base = blockIdx.x * 128;
    const int nvalid = min(128, Ee - base);

    const uint32_t swh = smem_u32(sWeh), swl = smem_u32(sWel);
    for (int i = tid; i < 640; i += 256) {
        cp_async16(swh + i * 16, (const char*)Weh + i * 16);
        cp_async16(swl + i * 16, (const char*)Wel + i * 16);
    }
    cp_commit();

    if (tid < 128) {
        sbias[tid] = be[tid];
        int e = min(base + tid, Ee - 1);
        ssrc[tid] = src[e];
        sdst[tid] = dst[e];
    }

    {
        const int edge = tid >> 1, half = tid & 1;
        int ge = min(base + edge, Ee - 1);
        const float4* ap = (const float4*)(ef + (size_t)ge * 32 + half * 16);
        const uint32_t dh = smem_u32(sEfh) + edge * 80 + half * 32;
        const uint32_t dl = smem_u32(sEfl) + edge * 80 + half * 32;
#pragma unroll
        for (int i = 0; i < 4; i++) {
            float4 v = ap[i];
            uint32_t l0, l1;
            uint32_t h0 = split_hi2(v.x, v.y, l0);
            uint32_t h1 = split_hi2(v.z, v.w, l1);
            asm volatile("st.shared.v2.b32 [%0], {%1, %2};"
                         :: "r"(dh + i * 8), "r"(h0), "r"(h1));
            asm volatile("st.shared.v2.b32 [%0], {%1, %2};"
                         :: "r"(dl + i * 8), "r"(l0), "r"(l1));
        }
    }
    cp_wait0();
    __syncthreads();

    const int g = lane >> 2, tq = lane & 3;
    const uint32_t aoff = smem_u32(sEfh)
        + (uint32_t)(wid * 16 + (lane & 15)) * 80 + ((lane >> 4) ? 16 : 0);
    const uint32_t aloff = aoff + (smem_u32(sEfl) - smem_u32(sEfh));
    const int brow = (lane & 7) + ((lane >> 4) << 3);
    const uint32_t boff = smem_u32(sWeh) + (uint32_t)brow * 80 + ((lane & 8) ? 16 : 0);
    const uint32_t bloff = boff + (smem_u32(sWel) - smem_u32(sWeh));

    float acc[16][4];
#pragma unroll
    for (int ni = 0; ni < 16; ni++) {
        float2 b = *(const float2*)(sbias + ni * 8 + tq * 2);
        acc[ni][0] = b.x; acc[ni][1] = b.y;
        acc[ni][2] = b.x; acc[ni][3] = b.y;
    }

#pragma unroll
    for (int ks = 0; ks < 2; ks++) {
        uint32_t ah[4], al[4];
        ldx4(ah, aoff + ks * 32);
        ldx4(al, aloff + ks * 32);
#pragma unroll
        for (int np = 0; np < 8; np++) {
            uint32_t rh[4], rl[4];
            ldx4(rh, boff + np * (16 * 80) + ks * 32);
            ldx4(rl, bloff + np * (16 * 80) + ks * 32);
            uint32_t bh0[2] = {rh[0], rh[1]}, bh1[2] = {rh[2], rh[3]};
            uint32_t bl0[2] = {rl[0], rl[1]}, bl1[2] = {rl[2], rl[3]};
            mma_bf16(acc[np * 2],     ah, bh0);
            mma_bf16(acc[np * 2],     ah, bl0);
            mma_bf16(acc[np * 2],     al, bh0);
            mma_bf16(acc[np * 2 + 1], ah, bh1);
            mma_bf16(acc[np * 2 + 1], ah, bl1);
            mma_bf16(acc[np * 2 + 1], al, bh1);
        }
    }

    // lane-pair merge -> float4 ownership
    const bool evn = ((lane & 1) == 0);
    float4 rowA[8], rowB[8];
#pragma unroll
    for (int i = 0; i < 8; i++) {
        float s0 = evn ? acc[i + 8][0] : acc[i][0];
        float s1 = evn ? acc[i + 8][1] : acc[i][1];
        float s2 = evn ? acc[i + 8][2] : acc[i][2];
        float s3 = evn ? acc[i + 8][3] : acc[i][3];
        float g0 = __shfl_xor_sync(0xffffffffu, s0, 1);
        float g1 = __shfl_xor_sync(0xffffffffu, s1, 1);
        float g2 = __shfl_xor_sync(0xffffffffu, s2, 1);
        float g3 = __shfl_xor_sync(0xffffffffu, s3, 1);
        float k0 = evn ? acc[i][0] : acc[i + 8][0];
        float k1 = evn ? acc[i][1] : acc[i + 8][1];
        float k2 = evn ? acc[i][2] : acc[i + 8][2];
        float k3 = evn ? acc[i][3] : acc[i + 8][3];
        rowA[i] = evn ? make_float4(k0, k1, g0, g1) : make_float4(g0, g1, k0, k1);
        rowB[i] = evn ? make_float4(k2, k3, g2, g3) : make_float4(g2, g3, k2, k3);
    }
    const int nk0 = evn ? 0 : 8;
    const int jq  = (lane >> 1) & 1;

    const int er0 = wid * 16 + g;
#pragma unroll
    for (int half = 0; half < 2; half++) {
        const int er = er0 + half * 8;
        if (er < nvalid) {
            const size_t srow = (size_t)ssrc[er] * 128;
            const size_t drow = (size_t)sdst[er] * 128;
#pragma unroll
            for (int i = 0; i < 8; i++) {
                const int cb = (nk0 + i) * 8 + 4 * jq;
                float4 ev = half ? rowB[i] : rowA[i];
                float4 xv = *(const float4*)(xin + srow + cb);
                float4 m;
                m.x = fmaxf(xv.x + ev.x, 0.f);
                m.y = fmaxf(xv.y + ev.y, 0.f);
                m.z = fmaxf(xv.z + ev.z, 0.f);
                m.w = fmaxf(xv.w + ev.w, 0.f);
                red_add_v4(agg + drow + cb, m);
            }
        }
    }
}

// ---------------- shared GEMM pieces -------------------------------------------
template <int NF>
__device__ __forceinline__ void mma_stage(
    uint32_t sAh, uint32_t sAl, uint32_t sWh, uint32_t sWl,
    uint32_t aoff, int cw, int lane, const float* __restrict__ bias,
    float (&acc)[4][NF][4]) {
    const int tq = lane & 3;
    const int brow = (lane & 7) + ((lane >> 4) << 3);
    const uint32_t boff = (uint32_t)(cw * (8 * NF) + brow) * 272
                        + ((lane & 8) ? 16 : 0);
#pragma unroll
    for (int ni = 0; ni < NF; ni++) {
        float2 b = __ldg((const float2*)(bias + cw * (8 * NF) + ni * 8 + tq * 2));
#pragma unroll
        for (int mi = 0; mi < 4; mi++) {
            acc[mi][ni][0] = b.x; acc[mi][ni][1] = b.y;
            acc[mi][ni][2] = b.x; acc[mi][ni][3] = b.y;
        }
    }
#pragma unroll
    for (int ks = 0; ks < 8; ks++) {
        uint32_t ah[4][4], al[4][4], bh[NF][2], bl[NF][2];
#pragma unroll
        for (int mi = 0; mi < 4; mi++) {
            ldx4(ah[mi], sAh + aoff + mi * 4352 + ks * 32);
            ldx4(al[mi], sAl + aoff + mi * 4352 + ks * 32);
        }
#pragma unroll
        for (int np = 0; np < NF / 2; np++) {
            uint32_t r[4];
            ldx4(r, sWh + boff + np * 4352 + ks * 32);
            bh[np * 2][0] = r[0]; bh[np * 2][1] = r[1];
            bh[np * 2 + 1][0] = r[2]; bh[np * 2 + 1][1] = r[3];
            ldx4(r, sWl + boff + np * 4352 + ks * 32);
            bl[np * 2][0] = r[0]; bl[np * 2][1] = r[1];
            bl[np * 2 + 1][0] = r[2]; bl[np * 2 + 1][1] = r[3];
        }
#pragma unroll
        for (int mi = 0; mi < 4; mi++)
#pragma unroll
            for (int ni = 0; ni < NF; ni++) {
                mma_bf16(acc[mi][ni], ah[mi], bh[ni]);
                mma_bf16(acc[mi][ni], ah[mi], bl[ni]);
                mma_bf16(acc[mi][ni], al[mi], bh[ni]);
            }
    }
}

template <int ACT>
__device__ __forceinline__ void twrite(
    float (&acc)[4][4][4], uint32_t sAh, uint32_t sAl, int cw, int lane) {
    const int g = lane >> 2, tq = lane & 3;
#pragma unroll
    for (int mi = 0; mi < 4; mi++) {
        const int r0 = mi * 16 + g;
#pragma unroll
        for (int ni = 0; ni < 4; ni++) {
            const int col = cw * 32 + ni * 8 + tq * 2;
            float v0 = acc[mi][ni][0], v1 = acc[mi][ni][1];
            float v2 = acc[mi][ni][2], v3 = acc[mi][ni][3];
            if (ACT == 1) {
                v0 = fmaxf(v0, 0.f); v1 = fmaxf(v1, 0.f);
                v2 = fmaxf(v2, 0.f); v3 = fmaxf(v3, 0.f);
            } else {
                v0 = tanhf(v0); v1 = tanhf(v1);
                v2 = tanhf(v2); v3 = tanhf(v3);
            }
            uint32_t lo0, lo1;
            uint32_t hi0 = split_hi2(v0, v1, lo0);
            uint32_t hi1 = split_hi2(v2, v3, lo1);
            const uint32_t d0 = (uint32_t)r0 * 272 + col * 2;
            asm volatile("st.shared.b32 [%0], %1;" :: "r"(sAh + d0), "r"(hi0));
            asm volatile("st.shared.b32 [%0], %1;" :: "r"(sAl + d0), "r"(lo0));
            asm volatile("st.shared.b32 [%0], %1;" :: "r"(sAh + d0 + 8 * 272), "r"(hi1));
            asm volatile("st.shared.b32 [%0], %1;" :: "r"(sAl + d0 + 8 * 272), "r"(lo1));
        }
    }
}

__device__ __forceinline__ void aconvert(
    const float* __restrict__ A, int mbase, int nrows,
    uint32_t sAh, uint32_t sAl, int tid) {
    const int row = tid >> 1, half = tid & 1;
    int grow = min(mbase + row, nrows - 1);
    const float* ap = A + (size_t)grow * 128 + half * 64;
    const uint32_t d = row * 272 + half * 128;
#pragma unroll
    for (int i = 0; i < 8; i++) {
        float4 v0 = *(const float4*)(ap + i * 8);
        float4 v1 = *(const float4*)(ap + i * 8 + 4);
        uint32_t l0, l1, l2, l3;
        uint32_t h0 = split_hi2(v0.x, v0.y, l0);
        uint32_t h1 = split_hi2(v0.z, v0.w, l1);
        uint32_t h2 = split_hi2(v1.x, v1.y, l2);
        uint32_t h3 = split_hi2(v1.z, v1.w, l3);
        asm volatile("st.shared.v4.b32 [%0], {%1, %2, %3, %4};"
                     :: "r"(sAh + d + i * 16), "r"(h0), "r"(h1), "r"(h2), "r"(h3));
        asm volatile("st.shared.v4.b32 [%0], {%1, %2, %3, %4};"
                     :: "r"(sAl + d + i * 16), "r"(l0), "r"(l1), "r"(l2), "r"(l3));
    }
}

// ---------------- two-stage fused node GEMM (dynamic tile scheduler) -----------
template <int COUT2, int ACT1, int ACT2>
__global__ void __launch_bounds__(128, 2)
fgemm(const float* __restrict__ A,
      const __nv_bfloat16* __restrict__ W1, const __nv_bfloat16* __restrict__ W2,
      const float* __restrict__ b1, const float* __restrict__ b2,
      float* __restrict__ out, float* __restrict__ out2, int nrows, int ntiles,
      int* __restrict__ tc) {
    constexpr int NW2 = COUT2 / 4;
    constexpr int NF2 = NW2 / 8;
    constexpr uint32_t AB  = 64 * 272;
    constexpr uint32_t WHB = 128 * 272;
    constexpr uint32_t WBYTES = 2 * WHB;

    extern __shared__ char sm[];
    const uint32_t s0  = smem_u32(sm);
    const uint32_t sAh = s0, sAl = s0 + AB;
    const uint32_t sWh = s0 + 2 * AB, sWl = sWh + WHB;
    __shared__ __align__(8) unsigned long long bw_store;
    __shared__ int s_mt;
    const uint32_t bw = smem_u32(&bw_store);

    const int tid  = threadIdx.x;
    const int lane = tid & 31;
    const int cw   = tid >> 5;
    const int g = lane >> 2, tq = lane & 3;
    const uint32_t aoff = (uint32_t)(lane & 15) * 272 + ((lane >> 4) ? 16 : 0);

    if (tid == 0) mbar_init(bw, 1);
    __syncthreads();
    if (tid == 0) { mbar_expect(bw, WBYTES); bulk_ld(sWh, W1, WBYTES, bw); }

    int ph = 0;
    for (;;) {
        if (tid == 0) s_mt = atomicAdd(tc, 1);
        __syncthreads();
        const int mt = s_mt;
        if (mt >= ntiles) break;
        const int mbase = mt * 64;

        aconvert(A, mbase, nrows, sAh, sAl, tid);
        __syncthreads();
        mbar_wait(bw, ph & 1); ph++;

        float acc[4][4][4];
        mma_stage<4>(sAh, sAl, sWh, sWl, aoff, cw, lane, b1, acc);
        __syncthreads();
        if (tid == 0) { mbar_expect(bw, WBYTES); bulk_ld(sWh, W2, WBYTES, bw); }
        twrite<ACT1>(acc, sAh, sAl, cw, lane);
        __syncthreads();
        mbar_wait(bw, ph & 1); ph++;

        float acc2[4][NF2][4];
        mma_stage<NF2>(sAh, sAl, sWh, sWl, aoff, cw, lane, b2, acc2);
        __syncthreads();
        if (tid == 0) { mbar_expect(bw, WBYTES); bulk_ld(sWh, W1, WBYTES, bw); }
#pragma unroll
        for (int mi = 0; mi < 4; mi++) {
            const int r0 = mbase + mi * 16 + g;
#pragma unroll
            for (int ni = 0; ni < NF2; ni++) {
                const int col = cw * NW2 + ni * 8 + tq * 2;
                float v0 = acc2[mi][ni][0], v1 = acc2[mi][ni][1];
                float v2 = acc2[mi][ni][2], v3 = acc2[mi][ni][3];
                if (ACT2 == 2) {
                    v0 = tanhf(v0); v1 = tanhf(v1);
                    v2 = tanhf(v2); v3 = tanhf(v3);
                }
                if (r0 < nrows) {
                    *(float2*)(out + (size_t)r0 * COUT2 + col) = make_float2(v0, v1);
                    if (out2)
                        *(float2*)(out2 + (size_t)r0 * COUT2 + col) = make_float2(v0, v1);
                }
                if (r0 + 8 < nrows) {
                    *(float2*)(out + (size_t)(r0 + 8) * COUT2 + col) = make_float2(v2, v3);
                    if (out2)
                        *(float2*)(out2 + (size_t)(r0 + 8) * COUT2 + col) = make_float2(v2, v3);
                }
            }
        }
    }
    mbar_wait(bw, ph & 1);       // drain speculative W1 bulk before exit
}

// ---------------- four-stage fused GEMM: layer2 MLP + head (dynamic sched) -----
__global__ void __launch_bounds__(128, 2)
fgemm4(const float* __restrict__ A,
       const __nv_bfloat16* __restrict__ Wa, const __nv_bfloat16* __restrict__ Wb,
       const __nv_bfloat16* __restrict__ Wc, const __nv_bfloat16* __restrict__ Wd,
       const float* __restrict__ ba, const float* __restrict__ bb,
       const float* __restrict__ bc, const float* __restrict__ bd,
       float* __restrict__ out, int nrows, int ntiles, int* __restrict__ tc) {
    constexpr uint32_t AB  = 64 * 272;
    constexpr uint32_t WHB = 128 * 272;
    constexpr uint32_t WBYTES = 2 * WHB;

    extern __shared__ char sm[];
    const uint32_t s0  = smem_u32(sm);
    const uint32_t sAh = s0, sAl = s0 + AB;
    const uint32_t sWh = s0 + 2 * AB, sWl = sWh + WHB;
    __shared__ __align__(8) unsigned long long bw_store;
    __shared__ int s_mt;
    const uint32_t bw = smem_u32(&bw_store);

    const int tid  = threadIdx.x;
    const int lane = tid & 31;
    const int cw   = tid >> 5;
    const int g = lane >> 2, tq = lane & 3;
    const uint32_t aoff = (uint32_t)(lane & 15) * 272 + ((lane >> 4) ? 16 : 0);

    if (tid == 0) mbar_init(bw, 1);
    __syncthreads();
    if (tid == 0) { mbar_expect(bw, WBYTES); bulk_ld(sWh, Wa, WBYTES, bw); }

    int ph = 0;
    for (;;) {
        if (tid == 0) s_mt = atomicAdd(tc, 1);
        __syncthreads();
        const int mt = s_mt;
        if (mt >= ntiles) break;
        const int mbase = mt * 64;

        aconvert(A, mbase, nrows, sAh, sAl, tid);
        __syncthreads();
        mbar_wait(bw, ph & 1); ph++;

        {   // stage 1: relu(A@Wa+ba)
            float acc[4][4][4];
            mma_stage<4>(sAh, sAl, sWh, sWl, aoff, cw, lane, ba, acc);
            __syncthreads();
            if (tid == 0) { mbar_expect(bw, WBYTES); bulk_ld(sWh, Wb, WBYTES, bw); }
            twrite<1>(acc, sAh, sAl, cw, lane);
            __syncthreads();
            mbar_wait(bw, ph & 1); ph++;
        }
        {   // stage 2: tanh(T@Wb+bb)
            float acc[4][4][4];
            mma_stage<4>(sAh, sAl, sWh, sWl, aoff, cw, lane, bb, acc);
            __syncthreads();
            if (tid == 0) { mbar_expect(bw, WBYTES); bulk_ld(sWh, Wc, WBYTES, bw); }
            twrite<2>(acc, sAh, sAl, cw, lane);
            __syncthreads();
            mbar_wait(bw, ph & 1); ph++;
        }
        {   // stage 3: tanh(T@Wc+bc)
            float acc[4][4][4];
            mma_stage<4>(sAh, sAl, sWh, sWl, aoff, cw, lane, bc, acc);
            __syncthreads();
            if (tid == 0) { mbar_expect(bw, WBYTES); bulk_ld(sWh, Wd, WBYTES, bw); }
            twrite<2>(acc, sAh, sAl, cw, lane);
            __syncthreads();
            mbar_wait(bw, ph & 1); ph++;
        }
        {   // stage 4: T@Wd+bd -> out (COUT 64)
            float acc[4][2][4];
            mma_stage<2>(sAh, sAl, sWh, sWl, aoff, cw, lane, bd, acc);
            __syncthreads();
            if (tid == 0) { mbar_expect(bw, WBYTES); bulk_ld(sWh, Wa, WBYTES, bw); }
#pragma unroll
            for (int mi = 0; mi < 4; mi++) {
                const int r0 = mbase + mi * 16 + g;
#pragma unroll
                for (int ni = 0; ni < 2; ni++) {
                    const int col = cw * 16 + ni * 8 + tq * 2;
                    if (r0 < nrows)
                        *(float2*)(out + (size_t)r0 * 64 + col)
                            = make_float2(acc[mi][ni][0], acc[mi][ni][1]);
                    if (r0 + 8 < nrows)
                        *(float2*)(out + (size_t)(r0 + 8) * 64 + col)
                            = make_float2(acc[mi][ni][2], acc[mi][ni][3]);
                }
            }
        }
    }
    mbar_wait(bw, ph & 1);       // drain speculative Wa bulk before exit
}

// ---------------- launch ------------------------------------------------------
extern "C" void kernel_launch(void* const* d_in, const int* in_sizes, int n_in,
                              void* d_out, int out_size) {
    const float* x    = (const float*)d_in[0];
    const int*   ei   = (const int*)d_in[1];
    const float* ef   = (const float*)d_in[2];
    const float* We1  = (const float*)d_in[3];
    const float* be1  = (const float*)d_in[4];
    const float* W1a  = (const float*)d_in[5];
    const float* b1a  = (const float*)d_in[6];
    const float* W1b  = (const float*)d_in[7];
    const float* b1b  = (const float*)d_in[8];
    const float* We2  = (const float*)d_in[9];
    const float* be2  = (const float*)d_in[10];
    const float* W2a  = (const float*)d_in[11];
    const float* b2a  = (const float*)d_in[12];
    const float* W2b  = (const float*)d_in[13];
    const float* b2b  = (const float*)d_in[14];
    const float* Wfc1 = (const float*)d_in[15];
    const float* bfc1 = (const float*)d_in[16];
    const float* Wfc2 = (const float*)d_in[17];
    const float* bfc2 = (const float*)d_in[18];
    float* out = (float*)d_out;

    float *agg, *h;
    __nv_bfloat16 *wb, *web;
    int* tc;
    cudaGetSymbolAddress((void**)&agg, g_agg);
    cudaGetSymbolAddress((void**)&h,   g_h);
    cudaGetSymbolAddress((void**)&wb,  g_wb);
    cudaGetSymbolAddress((void**)&web, g_web);
    cudaGetSymbolAddress((void**)&tc,  g_tc);
    auto WB = [&](int m) { return wb + (size_t)m * 2 * 128 * 136; };
    auto WE = [&](int m, int s) { return web + ((size_t)m * 2 + s) * 128 * 40; };

    const int* srcp = ei;
    const int* dstp = ei + Ee;

    const int n4 = Nn * 128 / 4;
    const int cpG = (n4 + 255) / 256;
    const int egG = (Ee + 127) / 128;            // 4688
    const int ntiles = (Nn + 63) / 64;           // 1563
    const int gG = 296;

    constexpr int SMF = 2 * 17408 + 2 * 34816;   // 104448
    cudaFuncSetAttribute(fgemm<128, 1, 2>, cudaFuncAttributeMaxDynamicSharedMemorySize, SMF);
    cudaFuncSetAttribute(fgemm4, cudaFuncAttributeMaxDynamicSharedMemorySize, SMF);

    prep_all<<<385, 256>>>(W1a, W1b, W2a, W2b, Wfc1, Wfc2, We1, We2, wb, web, tc);

    // Layer 1: agg = x; agg += relu-msgs; h = tanh(relu(agg@W1a)@W1b); agg = h
    copy_kernel<<<cpG, 256>>>((float4*)agg, (const float4*)x, n4);
    edge_kernel<<<egG, 256>>>(x, srcp, dstp, ef, WE(0, 0), WE(0, 1), be1, agg);
    fgemm<128, 1, 2><<<gG, 128, SMF>>>(agg, WB(0), WB(1), b1a, b1b, h, agg,
                                       Nn, ntiles, tc + 0);

    // Layer 2 + head (fused): agg(=h) += msgs(h);
    // out = tanh(tanh(relu(agg@W2a)@W2b)@Wfc1)@Wfc2
    edge_kernel<<<egG, 256>>>(h, srcp, dstp, ef, WE(1, 0), WE(1, 1), be2, agg);
    fgemm4<<<gG, 128, SMF>>>(agg, WB(2), WB(3), WB(4), WB(5),
                             b2a, b2b, bfc1, bfc2, out, Nn, ntiles, tc + 1);
}

// round 14
// speedup vs baseline: 1.2064x; 1.0280x over previous
#include <cuda_runtime.h>
#include <cuda_bf16.h>
#include <cstdint>

#define Nn 100000
#define Ee 600000

// ---------------- scratch (allocation-free: __device__ globals) --------------
__device__ float g_agg[Nn * 128];
__device__ float g_h[Nn * 128];
__device__ __align__(16) __nv_bfloat16 g_wb[6][2][128 * 136];
__device__ __align__(16) __nv_bfloat16 g_web[2][2][128 * 40];
__device__ int g_tc[4];          // dynamic tile counters (zeroed by prep_all)

// ---------------- helpers -----------------------------------------------------
__device__ __forceinline__ void red_add_v4(float* p, float4 v) {
    asm volatile("red.global.add.v4.f32 [%0], {%1, %2, %3, %4};"
                 :: "l"(p), "f"(v.x), "f"(v.y), "f"(v.z), "f"(v.w)
                 : "memory");
}
__device__ __forceinline__ uint32_t smem_u32(const void* p) {
    return (uint32_t)__cvta_generic_to_shared(p);
}
__device__ __forceinline__ void cp_async16(uint32_t dst, const void* src) {
    asm volatile("cp.async.cg.shared.global [%0], [%1], 16;"
                 :: "r"(dst), "l"(src));
}
__device__ __forceinline__ void cp_commit() {
    asm volatile("cp.async.commit_group;");
}
__device__ __forceinline__ void cp_wait0() {
    asm volatile("cp.async.wait_group 0;" ::: "memory");
}
__device__ __forceinline__ void cp_wait1() {
    asm volatile("cp.async.wait_group 1;" ::: "memory");
}
__device__ __forceinline__ void ldx4(uint32_t* r, uint32_t addr) {
    asm volatile("ldmatrix.sync.aligned.m8n8.x4.shared.b16 {%0, %1, %2, %3}, [%4];"
                 : "=r"(r[0]), "=r"(r[1]), "=r"(r[2]), "=r"(r[3]) : "r"(addr));
}
__device__ __forceinline__ void mma_bf16(float* c, const uint32_t* a,
                                         const uint32_t* b) {
    asm volatile("mma.sync.aligned.m16n8k16.row.col.f32.bf16.bf16.f32 "
                 "{%0, %1, %2, %3}, {%4, %5, %6, %7}, {%8, %9}, {%0, %1, %2, %3};"
                 : "+f"(c[0]), "+f"(c[1]), "+f"(c[2]), "+f"(c[3])
                 : "r"(a[0]), "r"(a[1]), "r"(a[2]), "r"(a[3]),
                   "r"(b[0]), "r"(b[1]));
}
__device__ __forceinline__ uint32_t bf2_u32(__nv_bfloat162 x) {
    uint32_t r;
    memcpy(&r, &x, 4);
    return r;
}
__device__ __forceinline__ uint32_t split_hi2(float a, float b, uint32_t& lo) {
    __nv_bfloat162 h = __floats2bfloat162_rn(a, b);
    __nv_bfloat162 l = __floats2bfloat162_rn(a - __bfloat162float(h.x),
                                             b - __bfloat162float(h.y));
    lo = bf2_u32(l);
    return bf2_u32(h);
}
// ---- bulk copy + mbarrier ----
__device__ __forceinline__ void mbar_init(uint32_t mb, uint32_t cnt) {
    asm volatile("mbarrier.init.shared.b64 [%0], %1;" :: "r"(mb), "r"(cnt) : "memory");
}
__device__ __forceinline__ void mbar_expect(uint32_t mb, uint32_t bytes) {
    asm volatile("mbarrier.arrive.expect_tx.shared.b64 _, [%0], %1;"
                 :: "r"(mb), "r"(bytes) : "memory");
}
__device__ __forceinline__ void bulk_ld(uint32_t dst, const void* src,
                                        uint32_t bytes, uint32_t mb) {
    asm volatile("cp.async.bulk.shared::cta.global.mbarrier::complete_tx::bytes "
                 "[%0], [%1], %2, [%3];"
                 :: "r"(dst), "l"(src), "r"(bytes), "r"(mb) : "memory");
}
__device__ __forceinline__ void mbar_wait(uint32_t mb, uint32_t parity) {
    uint32_t done;
    asm volatile("{\n\t.reg .pred p;\n\t"
                 "mbarrier.try_wait.parity.acquire.cta.shared::cta.b64 p, [%1], %2;\n\t"
                 "selp.b32 %0, 1, 0, p;\n\t}"
                 : "=r"(done) : "r"(mb), "r"(parity) : "memory");
    if (!done) {
        asm volatile("{\n\t.reg .pred P1;\n\t"
                     "WL_%=:\n\t"
                     "mbarrier.try_wait.parity.acquire.cta.shared::cta.b64 P1, [%0], %1, 0x989680;\n\t"
                     "@P1 bra.uni WD_%=;\n\t"
                     "bra.uni WL_%=;\n\t"
                     "WD_%=:\n\t}"
                     :: "r"(mb), "r"(parity) : "memory");
    }
}

// ---------------- init copy ---------------------------------------------------
__global__ void __launch_bounds__(256) copy_kernel(float4* __restrict__ dst,
                                                   const float4* __restrict__ src,
                                                   int n4) {
    int i = blockIdx.x * blockDim.x + threadIdx.x;
    if (i < n4) dst[i] = src[i];
}

// ---------------- fused weight prep (one launch; also zeroes tile counters) ----
__global__ void __launch_bounds__(256)
prep_all(const float* __restrict__ W1a, const float* __restrict__ W1b,
         const float* __restrict__ W2a, const float* __restrict__ W2b,
         const float* __restrict__ Wfc1, const float* __restrict__ Wfc2,
         const float* __restrict__ We1, const float* __restrict__ We2,
         __nv_bfloat16* __restrict__ wb, __nv_bfloat16* __restrict__ web,
         int* __restrict__ tc) {
    int id = blockIdx.x * 256 + threadIdx.x;
    if (id < 81920) {
        int m = id / 16384, e = id % 16384;
        const float* W = (m == 0) ? W1a : (m == 1) ? W1b
                       : (m == 2) ? W2a : (m == 3) ? W2b : Wfc1;
        int n = e >> 7, k = e & 127;
        float v = W[k * 128 + n];
        __nv_bfloat16 h = __float2bfloat16_rn(v);
        __nv_bfloat16 l = __float2bfloat16_rn(v - __bfloat162float(h));
        wb[(size_t)m * 2 * 128 * 136 + n * 136 + k] = h;
        wb[((size_t)m * 2 + 1) * 128 * 136 + n * 136 + k] = l;
    } else if (id < 90112) {
        int e = id - 81920;
        int n = e >> 7, k = e & 127;
        float v = Wfc2[k * 64 + n];
        __nv_bfloat16 h = __float2bfloat16_rn(v);
        __nv_bfloat16 l = __float2bfloat16_rn(v - __bfloat162float(h));
        wb[(size_t)5 * 2 * 128 * 136 + n * 136 + k] = h;
        wb[((size_t)5 * 2 + 1) * 128 * 136 + n * 136 + k] = l;
    } else if (id < 98304) {
        int e = id - 90112;
        int m = e >> 12; e &= 4095;
        int n = e >> 5, k = e & 31;
        const float* We = m ? We2 : We1;
        float v = We[k * 128 + n];
        __nv_bfloat16 h = __float2bfloat16_rn(v);
        __nv_bfloat16 l = __float2bfloat16_rn(v - __bfloat162float(h));
        web[(size_t)m * 2 * 128 * 40 + n * 40 + k] = h;
        web[((size_t)m * 2 + 1) * 128 * 40 + n * 40 + k] = l;
    } else if (id < 98308) {
        tc[id - 98304] = 0;
    }
}

// ---------------- persistent HMMA fused edge kernel ----------------------------
// grid=296, 2 CTAs/SM. We/bias resident; ef fp32 + src/dst double-buffered
// via cp.async one chunk ahead. MMA + merge + register epilogue = R11 exact.
// Dynamic smem (76288 B):
//   [0,10240) We-hi [10240,20480) We-lo [20480,30720) ef-hi [30720,40960) ef-lo
//   [40960,73728) sF[2]: fp32 ef staging 16384 each
//   [73728,74240) bias  [74240,76288) idx[2]: src[128]+dst[128] each
__global__ void __launch_bounds__(256, 2)
edge_kernel(const float* __restrict__ xin,
            const int* __restrict__ src, const int* __restrict__ dst,
            const float* __restrict__ ef,
            const __nv_bfloat16* __restrict__ Weh,
            const __nv_bfloat16* __restrict__ Wel,
            const float* __restrict__ be,
            float* __restrict__ agg, int nchunks) {
    extern __shared__ char sm[];
    const uint32_t s0   = smem_u32(sm);
    const uint32_t sWeh = s0, sWel = s0 + 10240;
    const uint32_t sEfh = s0 + 20480, sEfl = s0 + 30720;
    float* sbias = (float*)(sm + 73728);

    const int tid  = threadIdx.x;
    const int wid  = tid >> 5;
    const int lane = tid & 31;

    auto issue_chunk = [&](int c, int buf) {
        if (c < nchunks) {
            const uint32_t dF = s0 + 40960 + buf * 16384;
            const size_t efmax = (size_t)Ee * 128 - 16;
#pragma unroll
            for (int i = 0; i < 4; i++) {
                int j = tid + i * 256;
                size_t bo = (size_t)c * 16384 + (size_t)j * 16;
                if (bo > efmax) bo = efmax;
                cp_async16(dF + j * 16, (const char*)ef + bo);
            }
            if (tid < 64) {
                const char* sp = (const char*)((tid < 32) ? src : dst);
                int t = tid & 31;
                size_t bo = (size_t)c * 512 + (size_t)t * 16;
                const size_t imax = (size_t)Ee * 4 - 16;
                if (bo > imax) bo = imax;
                cp_async16(s0 + 74240 + buf * 1024 + (tid < 32 ? 0 : 512) + t * 16,
                           sp + bo);
            }
        }
        cp_commit();
    };

    // resident We (folded into first chunk's group)
    for (int i = tid; i < 640; i += 256) {
        cp_async16(sWeh + i * 16, (const char*)Weh + i * 16);
        cp_async16(sWel + i * 16, (const char*)Wel + i * 16);
    }
    {
        // group 0: We + chunk bid; group 1: chunk bid+grid
        const uint32_t dF = s0 + 40960;
        const size_t efmax = (size_t)Ee * 128 - 16;
        int c = blockIdx.x;
#pragma unroll
        for (int i = 0; i < 4; i++) {
            int j = tid + i * 256;
            size_t bo = (size_t)c * 16384 + (size_t)j * 16;
            if (bo > efmax) bo = efmax;
            cp_async16(dF + j * 16, (const char*)ef + bo);
        }
        if (tid < 64) {
            const char* sp = (const char*)((tid < 32) ? src : dst);
            int t = tid & 31;
            size_t bo = (size_t)c * 512 + (size_t)t * 16;
            const size_t imax = (size_t)Ee * 4 - 16;
            if (bo > imax) bo = imax;
            cp_async16(s0 + 74240 + (tid < 32 ? 0 : 512) + t * 16, sp + bo);
        }
        cp_commit();
        issue_chunk(blockIdx.x + gridDim.x, 1);
    }
    if (tid < 128) sbias[tid] = be[tid];

    const int g = lane >> 2, tq = lane & 3;
    const uint32_t aoff = sEfh
        + (uint32_t)(wid * 16 + (lane & 15)) * 80 + ((lane >> 4) ? 16 : 0);
    const uint32_t aloff = aoff + (sEfl - sEfh);
    const int brow = (lane & 7) + ((lane >> 4) << 3);
    const uint32_t boff = sWeh + (uint32_t)brow * 80 + ((lane & 8) ? 16 : 0);
    const uint32_t bloff = boff + (sWel - sWeh);
    const bool evn = ((lane & 1) == 0);
    const int nk0 = evn ? 0 : 8;
    const int jq  = (lane >> 1) & 1;
    const int er0 = wid * 16 + g;

    for (int it = 0;; it++) {
        const int c = blockIdx.x + it * gridDim.x;
        if (c >= nchunks) break;
        const int buf = it & 1;
        const int nvalid = min(128, Ee - c * 128);

        cp_wait1();            // chunk c staged (c+grid may still fly)
        __syncthreads();

        // convert staged ef fp32 -> bf16 hi/lo tiles (pitch 40)
        {
            const int edge = tid >> 1, half = tid & 1;
            const float4* fp = (const float4*)(sm + 40960 + buf * 16384
                                               + edge * 128 + half * 64);
            const uint32_t dh = sEfh + edge * 80 + half * 32;
            const uint32_t dl = sEfl + edge * 80 + half * 32;
#pragma unroll
            for (int i = 0; i < 4; i++) {
                float4 v = fp[i];
                uint32_t l0, l1;
                uint32_t h0 = split_hi2(v.x, v.y, l0);
                uint32_t h1 = split_hi2(v.z, v.w, l1);
                asm volatile("st.shared.v2.b32 [%0], {%1, %2};"
                             :: "r"(dh + i * 8), "r"(h0), "r"(h1));
                asm volatile("st.shared.v2.b32 [%0], {%1, %2};"
                             :: "r"(dl + i * 8), "r"(l0), "r"(l1));
            }
        }
        // src/dst to registers (idx buffer gets overwritten by prefetch)
        const int* ib = (const int*)(sm + 74240 + buf * 1024);
        const int sA = ib[er0],       sB = ib[er0 + 8];
        const int dA = ib[128 + er0], dB = ib[128 + er0 + 8];
        __syncthreads();

        // MMA: e = ef @ We + be (bias-seeded accumulators)
        float acc[16][4];
#pragma unroll
        for (int ni = 0; ni < 16; ni++) {
            float2 b = *(const float2*)(sbias + ni * 8 + tq * 2);
            acc[ni][0] = b.x; acc[ni][1] = b.y;
            acc[ni][2] = b.x; acc[ni][3] = b.y;
        }
#pragma unroll
        for (int ks = 0; ks < 2; ks++) {
            uint32_t ah[4], al[4];
            ldx4(ah, aoff + ks * 32);
            ldx4(al, aloff + ks * 32);
#pragma unroll
            for (int np = 0; np < 8; np++) {
                uint32_t rh[4], rl[4];
                ldx4(rh, boff + np * (16 * 80) + ks * 32);
                ldx4(rl, bloff + np * (16 * 80) + ks * 32);
                uint32_t bh0[2] = {rh[0], rh[1]}, bh1[2] = {rh[2], rh[3]};
                uint32_t bl0[2] = {rl[0], rl[1]}, bl1[2] = {rl[2], rl[3]};
                mma_bf16(acc[np * 2],     ah, bh0);
                mma_bf16(acc[np * 2],     ah, bl0);
                mma_bf16(acc[np * 2],     al, bh0);
                mma_bf16(acc[np * 2 + 1], ah, bh1);
                mma_bf16(acc[np * 2 + 1], ah, bl1);
                mma_bf16(acc[np * 2 + 1], al, bh1);
            }
        }
        __syncthreads();       // tile reads done -> safe to restage buf

        // prefetch chunk c + 2*grid into this buffer
        issue_chunk(c + 2 * gridDim.x, buf);

        // lane-pair merge -> float4 ownership
        float4 rowA[8], rowB[8];
#pragma unroll
        for (int i = 0; i < 8; i++) {
            float s0v = evn ? acc[i + 8][0] : acc[i][0];
            float s1v = evn ? acc[i + 8][1] : acc[i][1];
            float s2v = evn ? acc[i + 8][2] : acc[i][2];
            float s3v = evn ? acc[i + 8][3] : acc[i][3];
            float g0 = __shfl_xor_sync(0xffffffffu, s0v, 1);
            float g1 = __shfl_xor_sync(0xffffffffu, s1v, 1);
            float g2 = __shfl_xor_sync(0xffffffffu, s2v, 1);
            float g3 = __shfl_xor_sync(0xffffffffu, s3v, 1);
            float k0 = evn ? acc[i][0] : acc[i + 8][0];
            float k1 = evn ? acc[i][1] : acc[i + 8][1];
            float k2 = evn ? acc[i][2] : acc[i + 8][2];
            float k3 = evn ? acc[i][3] : acc[i + 8][3];
            rowA[i] = evn ? make_float4(k0, k1, g0, g1) : make_float4(g0, g1, k0, k1);
            rowB[i] = evn ? make_float4(k2, k3, g2, g3) : make_float4(g2, g3, k2, k3);
        }

        // register epilogue (R11): batched gathers + red.add.v4
#pragma unroll
        for (int half = 0; half < 2; half++) {
            const int er = er0 + half * 8;
            if (er < nvalid) {
                const size_t srow = (size_t)(half ? sB : sA) * 128;
                const size_t drow = (size_t)(half ? dB : dA) * 128;
#pragma unroll
                for (int i = 0; i < 8; i++) {
                    const int cb = (nk0 + i) * 8 + 4 * jq;
                    float4 ev = half ? rowB[i] : rowA[i];
                    float4 xv = *(const float4*)(xin + srow + cb);
                    float4 m;
                    m.x = fmaxf(xv.x + ev.x, 0.f);
                    m.y = fmaxf(xv.y + ev.y, 0.f);
                    m.z = fmaxf(xv.z + ev.z, 0.f);
                    m.w = fmaxf(xv.w + ev.w, 0.f);
                    red_add_v4(agg + drow + cb, m);
                }
            }
        }
    }
    cp_wait0();                // drain speculative prefetch before exit
}

// ---------------- shared GEMM pieces -------------------------------------------
template <int NF>
__device__ __forceinline__ void mma_stage(
    uint32_t sAh, uint32_t sAl, uint32_t sWh, uint32_t sWl,
    uint32_t aoff, int cw, int lane, const float* __restrict__ bias,
    float (&acc)[4][NF][4]) {
    const int tq = lane & 3;
    const int brow = (lane & 7) + ((lane >> 4) << 3);
    const uint32_t boff = (uint32_t)(cw * (8 * NF) + brow) * 272
                        + ((lane & 8) ? 16 : 0);
#pragma unroll
    for (int ni = 0; ni < NF; ni++) {
        float2 b = __ldg((const float2*)(bias + cw * (8 * NF) + ni * 8 + tq * 2));
#pragma unroll
        for (int mi = 0; mi < 4; mi++) {
            acc[mi][ni][0] = b.x; acc[mi][ni][1] = b.y;
            acc[mi][ni][2] = b.x; acc[mi][ni][3] = b.y;
        }
    }
#pragma unroll
    for (int ks = 0; ks < 8; ks++) {
        uint32_t ah[4][4], al[4][4], bh[NF][2], bl[NF][2];
#pragma unroll
        for (int mi = 0; mi < 4; mi++) {
            ldx4(ah[mi], sAh + aoff + mi * 4352 + ks * 32);
            ldx4(al[mi], sAl + aoff + mi * 4352 + ks * 32);
        }
#pragma unroll
        for (int np = 0; np < NF / 2; np++) {
            uint32_t r[4];
            ldx4(r, sWh + boff + np * 4352 + ks * 32);
            bh[np * 2][0] = r[0]; bh[np * 2][1] = r[1];
            bh[np * 2 + 1][0] = r[2]; bh[np * 2 + 1][1] = r[3];
            ldx4(r, sWl + boff + np * 4352 + ks * 32);
            bl[np * 2][0] = r[0]; bl[np * 2][1] = r[1];
            bl[np * 2 + 1][0] = r[2]; bl[np * 2 + 1][1] = r[3];
        }
#pragma unroll
        for (int mi = 0; mi < 4; mi++)
#pragma unroll
            for (int ni = 0; ni < NF; ni++) {
                mma_bf16(acc[mi][ni], ah[mi], bh[ni]);
                mma_bf16(acc[mi][ni], ah[mi], bl[ni]);
                mma_bf16(acc[mi][ni], al[mi], bh[ni]);
            }
    }
}

template <int ACT>
__device__ __forceinline__ void twrite(
    float (&acc)[4][4][4], uint32_t sAh, uint32_t sAl, int cw, int lane) {
    const int g = lane >> 2, tq = lane & 3;
#pragma unroll
    for (int mi = 0; mi < 4; mi++) {
        const int r0 = mi * 16 + g;
#pragma unroll
        for (int ni = 0; ni < 4; ni++) {
            const int col = cw * 32 + ni * 8 + tq * 2;
            float v0 = acc[mi][ni][0], v1 = acc[mi][ni][1];
            float v2 = acc[mi][ni][2], v3 = acc[mi][ni][3];
            if (ACT == 1) {
                v0 = fmaxf(v0, 0.f); v1 = fmaxf(v1, 0.f);
                v2 = fmaxf(v2, 0.f); v3 = fmaxf(v3, 0.f);
            } else {
                v0 = tanhf(v0); v1 = tanhf(v1);
                v2 = tanhf(v2); v3 = tanhf(v3);
            }
            uint32_t lo0, lo1;
            uint32_t hi0 = split_hi2(v0, v1, lo0);
            uint32_t hi1 = split_hi2(v2, v3, lo1);
            const uint32_t d0 = (uint32_t)r0 * 272 + col * 2;
            asm volatile("st.shared.b32 [%0], %1;" :: "r"(sAh + d0), "r"(hi0));
            asm volatile("st.shared.b32 [%0], %1;" :: "r"(sAl + d0), "r"(lo0));
            asm volatile("st.shared.b32 [%0], %1;" :: "r"(sAh + d0 + 8 * 272), "r"(hi1));
            asm volatile("st.shared.b32 [%0], %1;" :: "r"(sAl + d0 + 8 * 272), "r"(lo1));
        }
    }
}

__device__ __forceinline__ void aconvert(
    const float* __restrict__ A, int mbase, int nrows,
    uint32_t sAh, uint32_t sAl, int tid) {
    const int row = tid >> 1, half = tid & 1;
    int grow = min(mbase + row, nrows - 1);
    const float* ap = A + (size_t)grow * 128 + half * 64;
    const uint32_t d = row * 272 + half * 128;
#pragma unroll
    for (int i = 0; i < 8; i++) {
        float4 v0 = *(const float4*)(ap + i * 8);
        float4 v1 = *(const float4*)(ap + i * 8 + 4);
        uint32_t l0, l1, l2, l3;
        uint32_t h0 = split_hi2(v0.x, v0.y, l0);
        uint32_t h1 = split_hi2(v0.z, v0.w, l1);
        uint32_t h2 = split_hi2(v1.x, v1.y, l2);
        uint32_t h3 = split_hi2(v1.z, v1.w, l3);
        asm volatile("st.shared.v4.b32 [%0], {%1, %2, %3, %4};"
                     :: "r"(sAh + d + i * 16), "r"(h0), "r"(h1), "r"(h2), "r"(h3));
        asm volatile("st.shared.v4.b32 [%0], {%1, %2, %3, %4};"
                     :: "r"(sAl + d + i * 16), "r"(l0), "r"(l1), "r"(l2), "r"(l3));
    }
}

// ---------------- two-stage fused node GEMM (dynamic tile scheduler) -----------
template <int COUT2, int ACT1, int ACT2>
__global__ void __launch_bounds__(128, 2)
fgemm(const float* __restrict__ A,
      const __nv_bfloat16* __restrict__ W1, const __nv_bfloat16* __restrict__ W2,
      const float* __restrict__ b1, const float* __restrict__ b2,
      float* __restrict__ out, float* __restrict__ out2, int nrows, int ntiles,
      int* __restrict__ tc) {
    constexpr int NW2 = COUT2 / 4;
    constexpr int NF2 = NW2 / 8;
    constexpr uint32_t AB  = 64 * 272;
    constexpr uint32_t WHB = 128 * 272;
    constexpr uint32_t WBYTES = 2 * WHB;

    extern __shared__ char sm[];
    const uint32_t s0  = smem_u32(sm);
    const uint32_t sAh = s0, sAl = s0 + AB;
    const uint32_t sWh = s0 + 2 * AB, sWl = sWh + WHB;
    __shared__ __align__(8) unsigned long long bw_store;
    __shared__ int s_mt;
    const uint32_t bw = smem_u32(&bw_store);

    const int tid  = threadIdx.x;
    const int lane = tid & 31;
    const int cw   = tid >> 5;
    const int g = lane >> 2, tq = lane & 3;
    const uint32_t aoff = (uint32_t)(lane & 15) * 272 + ((lane >> 4) ? 16 : 0);

    if (tid == 0) mbar_init(bw, 1);
    __syncthreads();
    if (tid == 0) { mbar_expect(bw, WBYTES); bulk_ld(sWh, W1, WBYTES, bw); }

    int ph = 0;
    for (;;) {
        if (tid == 0) s_mt = atomicAdd(tc, 1);
        __syncthreads();
        const int mt = s_mt;
        if (mt >= ntiles) break;
        const int mbase = mt * 64;

        aconvert(A, mbase, nrows, sAh, sAl, tid);
        __syncthreads();
        mbar_wait(bw, ph & 1); ph++;

        float acc[4][4][4];
        mma_stage<4>(sAh, sAl, sWh, sWl, aoff, cw, lane, b1, acc);
        __syncthreads();
        if (tid == 0) { mbar_expect(bw, WBYTES); bulk_ld(sWh, W2, WBYTES, bw); }
        twrite<ACT1>(acc, sAh, sAl, cw, lane);
        __syncthreads();
        mbar_wait(bw, ph & 1); ph++;

        float acc2[4][NF2][4];
        mma_stage<NF2>(sAh, sAl, sWh, sWl, aoff, cw, lane, b2, acc2);
        __syncthreads();
        if (tid == 0) { mbar_expect(bw, WBYTES); bulk_ld(sWh, W1, WBYTES, bw); }
#pragma unroll
        for (int mi = 0; mi < 4; mi++) {
            const int r0 = mbase + mi * 16 + g;
#pragma unroll
            for (int ni = 0; ni < NF2; ni++) {
                const int col = cw * NW2 + ni * 8 + tq * 2;
                float v0 = acc2[mi][ni][0], v1 = acc2[mi][ni][1];
                float v2 = acc2[mi][ni][2], v3 = acc2[mi][ni][3];
                if (ACT2 == 2) {
                    v0 = tanhf(v0); v1 = tanhf(v1);
                    v2 = tanhf(v2); v3 = tanhf(v3);
                }
                if (r0 < nrows) {
                    *(float2*)(out + (size_t)r0 * COUT2 + col) = make_float2(v0, v1);
                    if (out2)
                        *(float2*)(out2 + (size_t)r0 * COUT2 + col) = make_float2(v0, v1);
                }
                if (r0 + 8 < nrows) {
                    *(float2*)(out + (size_t)(r0 + 8) * COUT2 + col) = make_float2(v2, v3);
                    if (out2)
                        *(float2*)(out2 + (size_t)(r0 + 8) * COUT2 + col) = make_float2(v2, v3);
                }
            }
        }
    }
    mbar_wait(bw, ph & 1);       // drain speculative W1 bulk before exit
}

// ---------------- four-stage fused GEMM: layer2 MLP + head (dynamic sched) -----
__global__ void __launch_bounds__(128, 2)
fgemm4(const float* __restrict__ A,
       const __nv_bfloat16* __restrict__ Wa, const __nv_bfloat16* __restrict__ Wb,
       const __nv_bfloat16* __restrict__ Wc, const __nv_bfloat16* __restrict__ Wd,
       const float* __restrict__ ba, const float* __restrict__ bb,
       const float* __restrict__ bc, const float* __restrict__ bd,
       float* __restrict__ out, int nrows, int ntiles, int* __restrict__ tc) {
    constexpr uint32_t AB  = 64 * 272;
    constexpr uint32_t WHB = 128 * 272;
    constexpr uint32_t WBYTES = 2 * WHB;

    extern __shared__ char sm[];
    const uint32_t s0  = smem_u32(sm);
    const uint32_t sAh = s0, sAl = s0 + AB;
    const uint32_t sWh = s0 + 2 * AB, sWl = sWh + WHB;
    __shared__ __align__(8) unsigned long long bw_store;
    __shared__ int s_mt;
    const uint32_t bw = smem_u32(&bw_store);

    const int tid  = threadIdx.x;
    const int lane = tid & 31;
    const int cw   = tid >> 5;
    const int g = lane >> 2, tq = lane & 3;
    const uint32_t aoff = (uint32_t)(lane & 15) * 272 + ((lane >> 4) ? 16 : 0);

    if (tid == 0) mbar_init(bw, 1);
    __syncthreads();
    if (tid == 0) { mbar_expect(bw, WBYTES); bulk_ld(sWh, Wa, WBYTES, bw); }

    int ph = 0;
    for (;;) {
        if (tid == 0) s_mt = atomicAdd(tc, 1);
        __syncthreads();
        const int mt = s_mt;
        if (mt >= ntiles) break;
        const int mbase = mt * 64;

        aconvert(A, mbase, nrows, sAh, sAl, tid);
        __syncthreads();
        mbar_wait(bw, ph & 1); ph++;

        {   // stage 1: relu(A@Wa+ba)
            float acc[4][4][4];
            mma_stage<4>(sAh, sAl, sWh, sWl, aoff, cw, lane, ba, acc);
            __syncthreads();
            if (tid == 0) { mbar_expect(bw, WBYTES); bulk_ld(sWh, Wb, WBYTES, bw); }
            twrite<1>(acc, sAh, sAl, cw, lane);
            __syncthreads();
            mbar_wait(bw, ph & 1); ph++;
        }
        {   // stage 2: tanh(T@Wb+bb)
            float acc[4][4][4];
            mma_stage<4>(sAh, sAl, sWh, sWl, aoff, cw, lane, bb, acc);
            __syncthreads();
            if (tid == 0) { mbar_expect(bw, WBYTES); bulk_ld(sWh, Wc, WBYTES, bw); }
            twrite<2>(acc, sAh, sAl, cw, lane);
            __syncthreads();
            mbar_wait(bw, ph & 1); ph++;
        }
        {   // stage 3: tanh(T@Wc+bc)
            float acc[4][4][4];
            mma_stage<4>(sAh, sAl, sWh, sWl, aoff, cw, lane, bc, acc);
            __syncthreads();
            if (tid == 0) { mbar_expect(bw, WBYTES); bulk_ld(sWh, Wd, WBYTES, bw); }
            twrite<2>(acc, sAh, sAl, cw, lane);
            __syncthreads();
            mbar_wait(bw, ph & 1); ph++;
        }
        {   // stage 4: T@Wd+bd -> out (COUT 64)
            float acc[4][2][4];
            mma_stage<2>(sAh, sAl, sWh, sWl, aoff, cw, lane, bd, acc);
            __syncthreads();
            if (tid == 0) { mbar_expect(bw, WBYTES); bulk_ld(sWh, Wa, WBYTES, bw); }
#pragma unroll
            for (int mi = 0; mi < 4; mi++) {
                const int r0 = mbase + mi * 16 + g;
#pragma unroll
                for (int ni = 0; ni < 2; ni++) {
                    const int col = cw * 16 + ni * 8 + tq * 2;
                    if (r0 < nrows)
                        *(float2*)(out + (size_t)r0 * 64 + col)
                            = make_float2(acc[mi][ni][0], acc[mi][ni][1]);
                    if (r0 + 8 < nrows)
                        *(float2*)(out + (size_t)(r0 + 8) * 64 + col)
                            = make_float2(acc[mi][ni][2], acc[mi][ni][3]);
                }
            }
        }
    }
    mbar_wait(bw, ph & 1);       // drain speculative Wa bulk before exit
}

// ---------------- launch ------------------------------------------------------
extern "C" void kernel_launch(void* const* d_in, const int* in_sizes, int n_in,
                              void* d_out, int out_size) {
    const float* x    = (const float*)d_in[0];
    const int*   ei   = (const int*)d_in[1];
    const float* ef   = (const float*)d_in[2];
    const float* We1  = (const float*)d_in[3];
    const float* be1  = (const float*)d_in[4];
    const float* W1a  = (const float*)d_in[5];
    const float* b1a  = (const float*)d_in[6];
    const float* W1b  = (const float*)d_in[7];
    const float* b1b  = (const float*)d_in[8];
    const float* We2  = (const float*)d_in[9];
    const float* be2  = (const float*)d_in[10];
    const float* W2a  = (const float*)d_in[11];
    const float* b2a  = (const float*)d_in[12];
    const float* W2b  = (const float*)d_in[13];
    const float* b2b  = (const float*)d_in[14];
    const float* Wfc1 = (const float*)d_in[15];
    const float* bfc1 = (const float*)d_in[16];
    const float* Wfc2 = (const float*)d_in[17];
    const float* bfc2 = (const float*)d_in[18];
    float* out = (float*)d_out;

    float *agg, *h;
    __nv_bfloat16 *wb, *web;
    int* tc;
    cudaGetSymbolAddress((void**)&agg, g_agg);
    cudaGetSymbolAddress((void**)&h,   g_h);
    cudaGetSymbolAddress((void**)&wb,  g_wb);
    cudaGetSymbolAddress((void**)&web, g_web);
    cudaGetSymbolAddress((void**)&tc,  g_tc);
    auto WB = [&](int m) { return wb + (size_t)m * 2 * 128 * 136; };
    auto WE = [&](int m, int s) { return web + ((size_t)m * 2 + s) * 128 * 40; };

    const int* srcp = ei;
    const int* dstp = ei + Ee;

    const int n4 = Nn * 128 / 4;
    const int cpG = (n4 + 255) / 256;
    const int nchunks = (Ee + 127) / 128;        // 4688
    const int ntiles = (Nn + 63) / 64;           // 1563
    const int gG = 296;

    constexpr int SME = 76288;
    constexpr int SMF = 2 * 17408 + 2 * 34816;   // 104448
    cudaFuncSetAttribute(edge_kernel, cudaFuncAttributeMaxDynamicSharedMemorySize, SME);
    cudaFuncSetAttribute(fgemm<128, 1, 2>, cudaFuncAttributeMaxDynamicSharedMemorySize, SMF);
    cudaFuncSetAttribute(fgemm4, cudaFuncAttributeMaxDynamicSharedMemorySize, SMF);

    prep_all<<<385, 256>>>(W1a, W1b, W2a, W2b, Wfc1, Wfc2, We1, We2, wb, web, tc);

    // Layer 1: agg = x; agg += relu-msgs; h = tanh(relu(agg@W1a)@W1b); agg = h
    copy_kernel<<<cpG, 256>>>((float4*)agg, (const float4*)x, n4);
    edge_kernel<<<gG, 256, SME>>>(x, srcp, dstp, ef, WE(0, 0), WE(0, 1), be1,
                                  agg, nchunks);
    fgemm<128, 1, 2><<<gG, 128, SMF>>>(agg, WB(0), WB(1), b1a, b1b, h, agg,
                                       Nn, ntiles, tc + 0);

    // Layer 2 + head (fused): agg(=h) += msgs(h);
    // out = tanh(tanh(relu(agg@W2a)@W2b)@Wfc1)@Wfc2
    edge_kernel<<<gG, 256, SME>>>(h, srcp, dstp, ef, WE(1, 0), WE(1, 1), be2,
                                  agg, nchunks);
    fgemm4<<<gG, 128, SMF>>>(agg, WB(2), WB(3), WB(4), WB(5),
                             b2a, b2b, bfc1, bfc2, out, Nn, ntiles, tc + 1);
}

// round 15
// speedup vs baseline: 1.2075x; 1.0009x over previous
#include <cuda_runtime.h>
#include <cuda_bf16.h>
#include <cstdint>

#define Nn 100000
#define Ee 600000

// ---------------- scratch (allocation-free: __device__ globals) --------------
__device__ float g_agg[Nn * 128];
__device__ float g_h[Nn * 128];
__device__ __align__(16) __nv_bfloat16 g_wb[6][2][128 * 136];
__device__ __align__(16) __nv_bfloat16 g_web[2][2][128 * 40];
__device__ int g_tc[4];          // dynamic tile counters (zeroed by prep_all)

// ---------------- helpers -----------------------------------------------------
__device__ __forceinline__ void red_add_v4(float* p, float4 v) {
    asm volatile("red.global.add.v4.f32 [%0], {%1, %2, %3, %4};"
                 :: "l"(p), "f"(v.x), "f"(v.y), "f"(v.z), "f"(v.w)
                 : "memory");
}
__device__ __forceinline__ uint32_t smem_u32(const void* p) {
    return (uint32_t)__cvta_generic_to_shared(p);
}
__device__ __forceinline__ void cp_async16(uint32_t dst, const void* src) {
    asm volatile("cp.async.cg.shared.global [%0], [%1], 16;"
                 :: "r"(dst), "l"(src));
}
__device__ __forceinline__ void cp_commit() {
    asm volatile("cp.async.commit_group;");
}
__device__ __forceinline__ void cp_wait0() {
    asm volatile("cp.async.wait_group 0;" ::: "memory");
}
__device__ __forceinline__ void cp_wait1() {
    asm volatile("cp.async.wait_group 1;" ::: "memory");
}
__device__ __forceinline__ void ldx4(uint32_t* r, uint32_t addr) {
    asm volatile("ldmatrix.sync.aligned.m8n8.x4.shared.b16 {%0, %1, %2, %3}, [%4];"
                 : "=r"(r[0]), "=r"(r[1]), "=r"(r[2]), "=r"(r[3]) : "r"(addr));
}
__device__ __forceinline__ void mma_bf16(float* c, const uint32_t* a,
                                         const uint32_t* b) {
    asm volatile("mma.sync.aligned.m16n8k16.row.col.f32.bf16.bf16.f32 "
                 "{%0, %1, %2, %3}, {%4, %5, %6, %7}, {%8, %9}, {%0, %1, %2, %3};"
                 : "+f"(c[0]), "+f"(c[1]), "+f"(c[2]), "+f"(c[3])
                 : "r"(a[0]), "r"(a[1]), "r"(a[2]), "r"(a[3]),
                   "r"(b[0]), "r"(b[1]));
}
__device__ __forceinline__ uint32_t bf2_u32(__nv_bfloat162 x) {
    uint32_t r;
    memcpy(&r, &x, 4);
    return r;
}
__device__ __forceinline__ uint32_t split_hi2(float a, float b, uint32_t& lo) {
    __nv_bfloat162 h = __floats2bfloat162_rn(a, b);
    __nv_bfloat162 l = __floats2bfloat162_rn(a - __bfloat162float(h.x),
                                             b - __bfloat162float(h.y));
    lo = bf2_u32(l);
    return bf2_u32(h);
}
// ---- bulk copy + mbarrier ----
__device__ __forceinline__ void mbar_init(uint32_t mb, uint32_t cnt) {
    asm volatile("mbarrier.init.shared.b64 [%0], %1;" :: "r"(mb), "r"(cnt) : "memory");
}
__device__ __forceinline__ void mbar_expect(uint32_t mb, uint32_t bytes) {
    asm volatile("mbarrier.arrive.expect_tx.shared.b64 _, [%0], %1;"
                 :: "r"(mb), "r"(bytes) : "memory");
}
__device__ __forceinline__ void bulk_ld(uint32_t dst, const void* src,
                                        uint32_t bytes, uint32_t mb) {
    asm volatile("cp.async.bulk.shared::cta.global.mbarrier::complete_tx::bytes "
                 "[%0], [%1], %2, [%3];"
                 :: "r"(dst), "l"(src), "r"(bytes), "r"(mb) : "memory");
}
__device__ __forceinline__ void mbar_wait(uint32_t mb, uint32_t parity) {
    uint32_t done;
    asm volatile("{\n\t.reg .pred p;\n\t"
                 "mbarrier.try_wait.parity.acquire.cta.shared::cta.b64 p, [%1], %2;\n\t"
                 "selp.b32 %0, 1, 0, p;\n\t}"
                 : "=r"(done) : "r"(mb), "r"(parity) : "memory");
    if (!done) {
        asm volatile("{\n\t.reg .pred P1;\n\t"
                     "WL_%=:\n\t"
                     "mbarrier.try_wait.parity.acquire.cta.shared::cta.b64 P1, [%0], %1, 0x989680;\n\t"
                     "@P1 bra.uni WD_%=;\n\t"
                     "bra.uni WL_%=;\n\t"
                     "WD_%=:\n\t}"
                     :: "r"(mb), "r"(parity) : "memory");
    }
}

// ---------------- fused weight prep + x->agg copy (one launch) -----------------
__global__ void __launch_bounds__(256)
prep_all(const float* __restrict__ W1a, const float* __restrict__ W1b,
         const float* __restrict__ W2a, const float* __restrict__ W2b,
         const float* __restrict__ Wfc1, const float* __restrict__ Wfc2,
         const float* __restrict__ We1, const float* __restrict__ We2,
         __nv_bfloat16* __restrict__ wb, __nv_bfloat16* __restrict__ web,
         int* __restrict__ tc,
         const float4* __restrict__ xsrc, float4* __restrict__ aggdst, int n4) {
    if (blockIdx.x >= 385) {          // copy region: agg = x
        int i = (blockIdx.x - 385) * 256 + threadIdx.x;
        if (i < n4) aggdst[i] = xsrc[i];
        return;
    }
    int id = blockIdx.x * 256 + threadIdx.x;
    if (id < 81920) {
        int m = id / 16384, e = id % 16384;
        const float* W = (m == 0) ? W1a : (m == 1) ? W1b
                       : (m == 2) ? W2a : (m == 3) ? W2b : Wfc1;
        int n = e >> 7, k = e & 127;
        float v = W[k * 128 + n];
        __nv_bfloat16 h = __float2bfloat16_rn(v);
        __nv_bfloat16 l = __float2bfloat16_rn(v - __bfloat162float(h));
        wb[(size_t)m * 2 * 128 * 136 + n * 136 + k] = h;
        wb[((size_t)m * 2 + 1) * 128 * 136 + n * 136 + k] = l;
    } else if (id < 90112) {
        int e = id - 81920;
        int n = e >> 7, k = e & 127;
        float v = Wfc2[k * 64 + n];
        __nv_bfloat16 h = __float2bfloat16_rn(v);
        __nv_bfloat16 l = __float2bfloat16_rn(v - __bfloat162float(h));
        wb[(size_t)5 * 2 * 128 * 136 + n * 136 + k] = h;
        wb[((size_t)5 * 2 + 1) * 128 * 136 + n * 136 + k] = l;
    } else if (id < 98304) {
        int e = id - 90112;
        int m = e >> 12; e &= 4095;
        int n = e >> 5, k = e & 31;
        const float* We = m ? We2 : We1;
        float v = We[k * 128 + n];
        __nv_bfloat16 h = __float2bfloat16_rn(v);
        __nv_bfloat16 l = __float2bfloat16_rn(v - __bfloat162float(h));
        web[(size_t)m * 2 * 128 * 40 + n * 40 + k] = h;
        web[((size_t)m * 2 + 1) * 128 * 40 + n * 40 + k] = l;
    } else if (id < 98308) {
        tc[id - 98304] = 0;
    }
}

// ---------------- persistent HMMA fused edge kernel (R14 exact) ----------------
__global__ void __launch_bounds__(256, 2)
edge_kernel(const float* __restrict__ xin,
            const int* __restrict__ src, const int* __restrict__ dst,
            const float* __restrict__ ef,
            const __nv_bfloat16* __restrict__ Weh,
            const __nv_bfloat16* __restrict__ Wel,
            const float* __restrict__ be,
            float* __restrict__ agg, int nchunks) {
    extern __shared__ char sm[];
    const uint32_t s0   = smem_u32(sm);
    const uint32_t sWeh = s0, sWel = s0 + 10240;
    const uint32_t sEfh = s0 + 20480, sEfl = s0 + 30720;
    float* sbias = (float*)(sm + 73728);

    const int tid  = threadIdx.x;
    const int wid  = tid >> 5;
    const int lane = tid & 31;

    auto issue_chunk = [&](int c, int buf) {
        if (c < nchunks) {
            const uint32_t dF = s0 + 40960 + buf * 16384;
            const size_t efmax = (size_t)Ee * 128 - 16;
#pragma unroll
            for (int i = 0; i < 4; i++) {
                int j = tid + i * 256;
                size_t bo = (size_t)c * 16384 + (size_t)j * 16;
                if (bo > efmax) bo = efmax;
                cp_async16(dF + j * 16, (const char*)ef + bo);
            }
            if (tid < 64) {
                const char* sp = (const char*)((tid < 32) ? src : dst);
                int t = tid & 31;
                size_t bo = (size_t)c * 512 + (size_t)t * 16;
                const size_t imax = (size_t)Ee * 4 - 16;
                if (bo > imax) bo = imax;
                cp_async16(s0 + 74240 + buf * 1024 + (tid < 32 ? 0 : 512) + t * 16,
                           sp + bo);
            }
        }
        cp_commit();
    };

    for (int i = tid; i < 640; i += 256) {
        cp_async16(sWeh + i * 16, (const char*)Weh + i * 16);
        cp_async16(sWel + i * 16, (const char*)Wel + i * 16);
    }
    {
        const uint32_t dF = s0 + 40960;
        const size_t efmax = (size_t)Ee * 128 - 16;
        int c = blockIdx.x;
#pragma unroll
        for (int i = 0; i < 4; i++) {
            int j = tid + i * 256;
            size_t bo = (size_t)c * 16384 + (size_t)j * 16;
            if (bo > efmax) bo = efmax;
            cp_async16(dF + j * 16, (const char*)ef + bo);
        }
        if (tid < 64) {
            const char* sp = (const char*)((tid < 32) ? src : dst);
            int t = tid & 31;
            size_t bo = (size_t)c * 512 + (size_t)t * 16;
            const size_t imax = (size_t)Ee * 4 - 16;
            if (bo > imax) bo = imax;
            cp_async16(s0 + 74240 + (tid < 32 ? 0 : 512) + t * 16, sp + bo);
        }
        cp_commit();
        issue_chunk(blockIdx.x + gridDim.x, 1);
    }
    if (tid < 128) sbias[tid] = be[tid];

    const int g = lane >> 2, tq = lane & 3;
    const uint32_t aoff = sEfh
        + (uint32_t)(wid * 16 + (lane & 15)) * 80 + ((lane >> 4) ? 16 : 0);
    const uint32_t aloff = aoff + (sEfl - sEfh);
    const int brow = (lane & 7) + ((lane >> 4) << 3);
    const uint32_t boff = sWeh + (uint32_t)brow * 80 + ((lane & 8) ? 16 : 0);
    const uint32_t bloff = boff + (sWel - sWeh);
    const bool evn = ((lane & 1) == 0);
    const int nk0 = evn ? 0 : 8;
    const int jq  = (lane >> 1) & 1;
    const int er0 = wid * 16 + g;

    for (int it = 0;; it++) {
        const int c = blockIdx.x + it * gridDim.x;
        if (c >= nchunks) break;
        const int buf = it & 1;
        const int nvalid = min(128, Ee - c * 128);

        cp_wait1();
        __syncthreads();

        {
            const int edge = tid >> 1, half = tid & 1;
            const float4* fp = (const float4*)(sm + 40960 + buf * 16384
                                               + edge * 128 + half * 64);
            const uint32_t dh = sEfh + edge * 80 + half * 32;
            const uint32_t dl = sEfl + edge * 80 + half * 32;
#pragma unroll
            for (int i = 0; i < 4; i++) {
                float4 v = fp[i];
                uint32_t l0, l1;
                uint32_t h0 = split_hi2(v.x, v.y, l0);
                uint32_t h1 = split_hi2(v.z, v.w, l1);
                asm volatile("st.shared.v2.b32 [%0], {%1, %2};"
                             :: "r"(dh + i * 8), "r"(h0), "r"(h1));
                asm volatile("st.shared.v2.b32 [%0], {%1, %2};"
                             :: "r"(dl + i * 8), "r"(l0), "r"(l1));
            }
        }
        const int* ib = (const int*)(sm + 74240 + buf * 1024);
        const int sA = ib[er0],       sB = ib[er0 + 8];
        const int dA = ib[128 + er0], dB = ib[128 + er0 + 8];
        __syncthreads();

        float acc[16][4];
#pragma unroll
        for (int ni = 0; ni < 16; ni++) {
            float2 b = *(const float2*)(sbias + ni * 8 + tq * 2);
            acc[ni][0] = b.x; acc[ni][1] = b.y;
            acc[ni][2] = b.x; acc[ni][3] = b.y;
        }
#pragma unroll
        for (int ks = 0; ks < 2; ks++) {
            uint32_t ah[4], al[4];
            ldx4(ah, aoff + ks * 32);
            ldx4(al, aloff + ks * 32);
#pragma unroll
            for (int np = 0; np < 8; np++) {
                uint32_t rh[4], rl[4];
                ldx4(rh, boff + np * (16 * 80) + ks * 32);
                ldx4(rl, bloff + np * (16 * 80) + ks * 32);
                uint32_t bh0[2] = {rh[0], rh[1]}, bh1[2] = {rh[2], rh[3]};
                uint32_t bl0[2] = {rl[0], rl[1]}, bl1[2] = {rl[2], rl[3]};
                mma_bf16(acc[np * 2],     ah, bh0);
                mma_bf16(acc[np * 2],     ah, bl0);
                mma_bf16(acc[np * 2],     al, bh0);
                mma_bf16(acc[np * 2 + 1], ah, bh1);
                mma_bf16(acc[np * 2 + 1], ah, bl1);
                mma_bf16(acc[np * 2 + 1], al, bh1);
            }
        }
        __syncthreads();

        issue_chunk(c + 2 * gridDim.x, buf);

        float4 rowA[8], rowB[8];
#pragma unroll
        for (int i = 0; i < 8; i++) {
            float s0v = evn ? acc[i + 8][0] : acc[i][0];
            float s1v = evn ? acc[i + 8][1] : acc[i][1];
            float s2v = evn ? acc[i + 8][2] : acc[i][2];
            float s3v = evn ? acc[i + 8][3] : acc[i][3];
            float g0 = __shfl_xor_sync(0xffffffffu, s0v, 1);
            float g1 = __shfl_xor_sync(0xffffffffu, s1v, 1);
            float g2 = __shfl_xor_sync(0xffffffffu, s2v, 1);
            float g3 = __shfl_xor_sync(0xffffffffu, s3v, 1);
            float k0 = evn ? acc[i][0] : acc[i + 8][0];
            float k1 = evn ? acc[i][1] : acc[i + 8][1];
            float k2 = evn ? acc[i][2] : acc[i + 8][2];
            float k3 = evn ? acc[i][3] : acc[i + 8][3];
            rowA[i] = evn ? make_float4(k0, k1, g0, g1) : make_float4(g0, g1, k0, k1);
            rowB[i] = evn ? make_float4(k2, k3, g2, g3) : make_float4(g2, g3, k2, k3);
        }

#pragma unroll
        for (int half = 0; half < 2; half++) {
            const int er = er0 + half * 8;
            if (er < nvalid) {
                const size_t srow = (size_t)(half ? sB : sA) * 128;
                const size_t drow = (size_t)(half ? dB : dA) * 128;
#pragma unroll
                for (int i = 0; i < 8; i++) {
                    const int cb = (nk0 + i) * 8 + 4 * jq;
                    float4 ev = half ? rowB[i] : rowA[i];
                    float4 xv = *(const float4*)(xin + srow + cb);
                    float4 m;
                    m.x = fmaxf(xv.x + ev.x, 0.f);
                    m.y = fmaxf(xv.y + ev.y, 0.f);
                    m.z = fmaxf(xv.z + ev.z, 0.f);
                    m.w = fmaxf(xv.w + ev.w, 0.f);
                    red_add_v4(agg + drow + cb, m);
                }
            }
        }
    }
    cp_wait0();
}

// ---------------- shared GEMM pieces -------------------------------------------
template <int NF>
__device__ __forceinline__ void mma_stage(
    uint32_t sAh, uint32_t sAl, uint32_t sWh, uint32_t sWl,
    uint32_t aoff, int cw, int lane, const float* __restrict__ bias,
    float (&acc)[4][NF][4]) {
    const int tq = lane & 3;
    const int brow = (lane & 7) + ((lane >> 4) << 3);
    const uint32_t boff = (uint32_t)(cw * (8 * NF) + brow) * 272
                        + ((lane & 8) ? 16 : 0);
#pragma unroll
    for (int ni = 0; ni < NF; ni++) {
        float2 b = __ldg((const float2*)(bias + cw * (8 * NF) + ni * 8 + tq * 2));
#pragma unroll
        for (int mi = 0; mi < 4; mi++) {
            acc[mi][ni][0] = b.x; acc[mi][ni][1] = b.y;
            acc[mi][ni][2] = b.x; acc[mi][ni][3] = b.y;
        }
    }
#pragma unroll
    for (int ks = 0; ks < 8; ks++) {
        uint32_t ah[4][4], al[4][4], bh[NF][2], bl[NF][2];
#pragma unroll
        for (int mi = 0; mi < 4; mi++) {
            ldx4(ah[mi], sAh + aoff + mi * 4352 + ks * 32);
            ldx4(al[mi], sAl + aoff + mi * 4352 + ks * 32);
        }
#pragma unroll
        for (int np = 0; np < NF / 2; np++) {
            uint32_t r[4];
            ldx4(r, sWh + boff + np * 4352 + ks * 32);
            bh[np * 2][0] = r[0]; bh[np * 2][1] = r[1];
            bh[np * 2 + 1][0] = r[2]; bh[np * 2 + 1][1] = r[3];
            ldx4(r, sWl + boff + np * 4352 + ks * 32);
            bl[np * 2][0] = r[0]; bl[np * 2][1] = r[1];
            bl[np * 2 + 1][0] = r[2]; bl[np * 2 + 1][1] = r[3];
        }
#pragma unroll
        for (int mi = 0; mi < 4; mi++)
#pragma unroll
            for (int ni = 0; ni < NF; ni++) {
                mma_bf16(acc[mi][ni], ah[mi], bh[ni]);
                mma_bf16(acc[mi][ni], ah[mi], bl[ni]);
                mma_bf16(acc[mi][ni], al[mi], bh[ni]);
            }
    }
}

template <int ACT>
__device__ __forceinline__ void twrite(
    float (&acc)[4][4][4], uint32_t sAh, uint32_t sAl, int cw, int lane) {
    const int g = lane >> 2, tq = lane & 3;
#pragma unroll
    for (int mi = 0; mi < 4; mi++) {
        const int r0 = mi * 16 + g;
#pragma unroll
        for (int ni = 0; ni < 4; ni++) {
            const int col = cw * 32 + ni * 8 + tq * 2;
            float v0 = acc[mi][ni][0], v1 = acc[mi][ni][1];
            float v2 = acc[mi][ni][2], v3 = acc[mi][ni][3];
            if (ACT == 1) {
                v0 = fmaxf(v0, 0.f); v1 = fmaxf(v1, 0.f);
                v2 = fmaxf(v2, 0.f); v3 = fmaxf(v3, 0.f);
            } else {
                v0 = tanhf(v0); v1 = tanhf(v1);
                v2 = tanhf(v2); v3 = tanhf(v3);
            }
            uint32_t lo0, lo1;
            uint32_t hi0 = split_hi2(v0, v1, lo0);
            uint32_t hi1 = split_hi2(v2, v3, lo1);
            const uint32_t d0 = (uint32_t)r0 * 272 + col * 2;
            asm volatile("st.shared.b32 [%0], %1;" :: "r"(sAh + d0), "r"(hi0));
            asm volatile("st.shared.b32 [%0], %1;" :: "r"(sAl + d0), "r"(lo0));
            asm volatile("st.shared.b32 [%0], %1;" :: "r"(sAh + d0 + 8 * 272), "r"(hi1));
            asm volatile("st.shared.b32 [%0], %1;" :: "r"(sAl + d0 + 8 * 272), "r"(lo1));
        }
    }
}

__device__ __forceinline__ void aconvert(
    const float* __restrict__ A, int mbase, int nrows,
    uint32_t sAh, uint32_t sAl, int tid) {
    const int row = tid >> 1, half = tid & 1;
    int grow = min(mbase + row, nrows - 1);
    const float* ap = A + (size_t)grow * 128 + half * 64;
    const uint32_t d = row * 272 + half * 128;
#pragma unroll
    for (int i = 0; i < 8; i++) {
        float4 v0 = *(const float4*)(ap + i * 8);
        float4 v1 = *(const float4*)(ap + i * 8 + 4);
        uint32_t l0, l1, l2, l3;
        uint32_t h0 = split_hi2(v0.x, v0.y, l0);
        uint32_t h1 = split_hi2(v0.z, v0.w, l1);
        uint32_t h2 = split_hi2(v1.x, v1.y, l2);
        uint32_t h3 = split_hi2(v1.z, v1.w, l3);
        asm volatile("st.shared.v4.b32 [%0], {%1, %2, %3, %4};"
                     :: "r"(sAh + d + i * 16), "r"(h0), "r"(h1), "r"(h2), "r"(h3));
        asm volatile("st.shared.v4.b32 [%0], {%1, %2, %3, %4};"
                     :: "r"(sAl + d + i * 16), "r"(l0), "r"(l1), "r"(l2), "r"(l3));
    }
}

// issue half-split W load: half0 -> mb0 (warps 0-1), half1 -> mb1 (warps 2-3)
__device__ __forceinline__ void loadW_split(
    const __nv_bfloat16* Wp, uint32_t sWh, uint32_t sWl,
    uint32_t mb0, uint32_t mb1, int tid) {
    const char* p = (const char*)Wp;
    if (tid == 0) {
        mbar_expect(mb0, 34816);
        bulk_ld(sWh, p, 17408, mb0);
        bulk_ld(sWl, p + 34816, 17408, mb0);
    }
    if (tid == 32) {
        mbar_expect(mb1, 34816);
        bulk_ld(sWh + 17408, p + 17408, 17408, mb1);
        bulk_ld(sWl + 17408, p + 34816 + 17408, 17408, mb1);
    }
}

// ---------------- two-stage fused node GEMM (dyn sched + W half-split) ---------
template <int COUT2, int ACT1, int ACT2>
__global__ void __launch_bounds__(128, 2)
fgemm(const float* __restrict__ A,
      const __nv_bfloat16* __restrict__ W1, const __nv_bfloat16* __restrict__ W2,
      const float* __restrict__ b1, const float* __restrict__ b2,
      float* __restrict__ out, float* __restrict__ out2, int nrows, int ntiles,
      int* __restrict__ tc) {
    constexpr int NW2 = COUT2 / 4;
    constexpr int NF2 = NW2 / 8;
    constexpr uint32_t AB  = 64 * 272;
    constexpr uint32_t WHB = 128 * 272;

    extern __shared__ char sm[];
    const uint32_t s0  = smem_u32(sm);
    const uint32_t sAh = s0, sAl = s0 + AB;
    const uint32_t sWh = s0 + 2 * AB, sWl = sWh + WHB;
    __shared__ __align__(8) unsigned long long bw_store[2];
    __shared__ int s_mt;
    const uint32_t bw0 = smem_u32(&bw_store[0]);
    const uint32_t bw1 = smem_u32(&bw_store[1]);

    const int tid  = threadIdx.x;
    const int lane = tid & 31;
    const int cw   = tid >> 5;
    const int g = lane >> 2, tq = lane & 3;
    const uint32_t aoff = (uint32_t)(lane & 15) * 272 + ((lane >> 4) ? 16 : 0);
    // stage-1/2 (COUT 128): warps 0-1 read n<64 (half0); warps 2-3 half1.
    // COUT 64 stage: all warps read n<64 -> half0.
    const uint32_t mybar128 = (cw < 2) ? bw0 : bw1;
    const uint32_t mybarL   = (COUT2 == 128) ? mybar128 : bw0;

    if (tid == 0) { mbar_init(bw0, 1); mbar_init(bw1, 1); }
    __syncthreads();
    loadW_split(W1, sWh, sWl, bw0, bw1, tid);

    int ph = 0;
    for (;;) {
        if (tid == 0) s_mt = atomicAdd(tc, 1);
        __syncthreads();
        const int mt = s_mt;
        if (mt >= ntiles) break;
        const int mbase = mt * 64;

        aconvert(A, mbase, nrows, sAh, sAl, tid);
        __syncthreads();
        mbar_wait(mybar128, ph & 1); ph++;

        float acc[4][4][4];
        mma_stage<4>(sAh, sAl, sWh, sWl, aoff, cw, lane, b1, acc);
        __syncthreads();
        loadW_split(W2, sWh, sWl, bw0, bw1, tid);
        twrite<ACT1>(acc, sAh, sAl, cw, lane);
        __syncthreads();
        mbar_wait(mybarL, ph & 1); ph++;

        float acc2[4][NF2][4];
        mma_stage<NF2>(sAh, sAl, sWh, sWl, aoff, cw, lane, b2, acc2);
        __syncthreads();
        loadW_split(W1, sWh, sWl, bw0, bw1, tid);
#pragma unroll
        for (int mi = 0; mi < 4; mi++) {
            const int r0 = mbase + mi * 16 + g;
#pragma unroll
            for (int ni = 0; ni < NF2; ni++) {
                const int col = cw * NW2 + ni * 8 + tq * 2;
                float v0 = acc2[mi][ni][0], v1 = acc2[mi][ni][1];
                float v2 = acc2[mi][ni][2], v3 = acc2[mi][ni][3];
                if (ACT2 == 2) {
                    v0 = tanhf(v0); v1 = tanhf(v1);
                    v2 = tanhf(v2); v3 = tanhf(v3);
                }
                if (r0 < nrows) {
                    *(float2*)(out + (size_t)r0 * COUT2 + col) = make_float2(v0, v1);
                    if (out2)
                        *(float2*)(out2 + (size_t)r0 * COUT2 + col) = make_float2(v0, v1);
                }
                if (r0 + 8 < nrows) {
                    *(float2*)(out + (size_t)(r0 + 8) * COUT2 + col) = make_float2(v2, v3);
                    if (out2)
                        *(float2*)(out2 + (size_t)(r0 + 8) * COUT2 + col) = make_float2(v2, v3);
                }
            }
        }
    }
    mbar_wait(bw0, ph & 1);      // drain speculative W1 bulks before exit
    mbar_wait(bw1, ph & 1);
}

// ---------------- four-stage fused GEMM (dyn sched + W half-split) -------------
__global__ void __launch_bounds__(128, 2)
fgemm4(const float* __restrict__ A,
       const __nv_bfloat16* __restrict__ Wa, const __nv_bfloat16* __restrict__ Wb,
       const __nv_bfloat16* __restrict__ Wc, const __nv_bfloat16* __restrict__ Wd,
       const float* __restrict__ ba, const float* __restrict__ bb,
       const float* __restrict__ bc, const float* __restrict__ bd,
       float* __restrict__ out, int nrows, int ntiles, int* __restrict__ tc) {
    constexpr uint32_t AB  = 64 * 272;
    constexpr uint32_t WHB = 128 * 272;

    extern __shared__ char sm[];
    const uint32_t s0  = smem_u32(sm);
    const uint32_t sAh = s0, sAl = s0 + AB;
    const uint32_t sWh = s0 + 2 * AB, sWl = sWh + WHB;
    __shared__ __align__(8) unsigned long long bw_store[2];
    __shared__ int s_mt;
    const uint32_t bw0 = smem_u32(&bw_store[0]);
    const uint32_t bw1 = smem_u32(&bw_store[1]);

    const int tid  = threadIdx.x;
    const int lane = tid & 31;
    const int cw   = tid >> 5;
    const int g = lane >> 2, tq = lane & 3;
    const uint32_t aoff = (uint32_t)(lane & 15) * 272 + ((lane >> 4) ? 16 : 0);
    const uint32_t mybar128 = (cw < 2) ? bw0 : bw1;

    if (tid == 0) { mbar_init(bw0, 1); mbar_init(bw1, 1); }
    __syncthreads();
    loadW_split(Wa, sWh, sWl, bw0, bw1, tid);

    int ph = 0;
    for (;;) {
        if (tid == 0) s_mt = atomicAdd(tc, 1);
        __syncthreads();
        const int mt = s_mt;
        if (mt >= ntiles) break;
        const int mbase = mt * 64;

        aconvert(A, mbase, nrows, sAh, sAl, tid);
        __syncthreads();
        mbar_wait(mybar128, ph & 1); ph++;

        {   // stage 1: relu(A@Wa+ba)
            float acc[4][4][4];
            mma_stage<4>(sAh, sAl, sWh, sWl, aoff, cw, lane, ba, acc);
            __syncthreads();
            loadW_split(Wb, sWh, sWl, bw0, bw1, tid);
            twrite<1>(acc, sAh, sAl, cw, lane);
            __syncthreads();
            mbar_wait(mybar128, ph & 1); ph++;
        }
        {   // stage 2: tanh(T@Wb+bb)
            float acc[4][4][4];
            mma_stage<4>(sAh, sAl, sWh, sWl, aoff, cw, lane, bb, acc);
            __syncthreads();
            loadW_split(Wc, sWh, sWl, bw0, bw1, tid);
            twrite<2>(acc, sAh, sAl, cw, lane);
            __syncthreads();
            mbar_wait(mybar128, ph & 1); ph++;
        }
        {   // stage 3: tanh(T@Wc+bc)
            float acc[4][4][4];
            mma_stage<4>(sAh, sAl, sWh, sWl, aoff, cw, lane, bc, acc);
            __syncthreads();
            loadW_split(Wd, sWh, sWl, bw0, bw1, tid);
            twrite<2>(acc, sAh, sAl, cw, lane);
            __syncthreads();
            mbar_wait(bw0, ph & 1); ph++;    // COUT 64: all warps read half0
        }
        {   // stage 4: T@Wd+bd -> out (COUT 64)
            float acc[4][2][4];
            mma_stage<2>(sAh, sAl, sWh, sWl, aoff, cw, lane, bd, acc);
            __syncthreads();
            loadW_split(Wa, sWh, sWl, bw0, bw1, tid);
#pragma unroll
            for (int mi = 0; mi < 4; mi++) {
                const int r0 = mbase + mi * 16 + g;
#pragma unroll
                for (int ni = 0; ni < 2; ni++) {
                    const int col = cw * 16 + ni * 8 + tq * 2;
                    if (r0 < nrows)
                        *(float2*)(out + (size_t)r0 * 64 + col)
                            = make_float2(acc[mi][ni][0], acc[mi][ni][1]);
                    if (r0 + 8 < nrows)
                        *(float2*)(out + (size_t)(r0 + 8) * 64 + col)
                            = make_float2(acc[mi][ni][2], acc[mi][ni][3]);
                }
            }
        }
    }
    mbar_wait(bw0, ph & 1);      // drain speculative Wa bulks before exit
    mbar_wait(bw1, ph & 1);
}

// ---------------- launch ------------------------------------------------------
extern "C" void kernel_launch(void* const* d_in, const int* in_sizes, int n_in,
                              void* d_out, int out_size) {
    const float* x    = (const float*)d_in[0];
    const int*   ei   = (const int*)d_in[1];
    const float* ef   = (const float*)d_in[2];
    const float* We1  = (const float*)d_in[3];
    const float* be1  = (const float*)d_in[4];
    const float* W1a  = (const float*)d_in[5];
    const float* b1a  = (const float*)d_in[6];
    const float* W1b  = (const float*)d_in[7];
    const float* b1b  = (const float*)d_in[8];
    const float* We2  = (const float*)d_in[9];
    const float* be2  = (const float*)d_in[10];
    const float* W2a  = (const float*)d_in[11];
    const float* b2a  = (const float*)d_in[12];
    const float* W2b  = (const float*)d_in[13];
    const float* b2b  = (const float*)d_in[14];
    const float* Wfc1 = (const float*)d_in[15];
    const float* bfc1 = (const float*)d_in[16];
    const float* Wfc2 = (const float*)d_in[17];
    const float* bfc2 = (const float*)d_in[18];
    float* out = (float*)d_out;

    float *agg, *h;
    __nv_bfloat16 *wb, *web;
    int* tc;
    cudaGetSymbolAddress((void**)&agg, g_agg);
    cudaGetSymbolAddress((void**)&h,   g_h);
    cudaGetSymbolAddress((void**)&wb,  g_wb);
    cudaGetSymbolAddress((void**)&web, g_web);
    cudaGetSymbolAddress((void**)&tc,  g_tc);
    auto WB = [&](int m) { return wb + (size_t)m * 2 * 128 * 136; };
    auto WE = [&](int m, int s) { return web + ((size_t)m * 2 + s) * 128 * 40; };

    const int* srcp = ei;
    const int* dstp = ei + Ee;

    const int n4 = Nn * 128 / 4;
    const int prepG = 385 + (n4 + 255) / 256;    // prep + fused x->agg copy
    const int nchunks = (Ee + 127) / 128;        // 4688
    const int ntiles = (Nn + 63) / 64;           // 1563
    const int gG = 296;

    constexpr int SME = 76288;
    constexpr int SMF = 2 * 17408 + 2 * 34816;   // 104448
    cudaFuncSetAttribute(edge_kernel, cudaFuncAttributeMaxDynamicSharedMemorySize, SME);
    cudaFuncSetAttribute(fgemm<128, 1, 2>, cudaFuncAttributeMaxDynamicSharedMemorySize, SMF);
    cudaFuncSetAttribute(fgemm4, cudaFuncAttributeMaxDynamicSharedMemorySize, SMF);

    // weight prep + tile-counter zero + agg = x copy, all in one launch
    prep_all<<<prepG, 256>>>(W1a, W1b, W2a, W2b, Wfc1, Wfc2, We1, We2, wb, web, tc,
                             (const float4*)x, (float4*)agg, n4);

    // Layer 1: agg(=x) += relu-msgs; h = tanh(relu(agg@W1a)@W1b); agg = h
    edge_kernel<<<gG, 256, SME>>>(x, srcp, dstp, ef, WE(0, 0), WE(0, 1), be1,
                                  agg, nchunks);
    fgemm<128, 1, 2><<<gG, 128, SMF>>>(agg, WB(0), WB(1), b1a, b1b, h, agg,
                                       Nn, ntiles, tc + 0);

    // Layer 2 + head (fused): agg(=h) += msgs(h);
    // out = tanh(tanh(relu(agg@W2a)@W2b)@Wfc1)@Wfc2
    edge_kernel<<<gG, 256, SME>>>(h, srcp, dstp, ef, WE(1, 0), WE(1, 1), be2,
                                  agg, nchunks);
    fgemm4<<<gG, 128, SMF>>>(agg, WB(2), WB(3), WB(4), WB(5),
                             b2a, b2b, bfc1, bfc2, out, Nn, ntiles, tc + 1);
}

// round 16
// speedup vs baseline: 1.2592x; 1.0428x over previous
#include <cuda_runtime.h>
#include <cuda_bf16.h>
#include <cstdint>

#define Nn 100000
#define Ee 600000

// ---------------- scratch (allocation-free: __device__ globals) --------------
__device__ float g_agg[Nn * 128];
__device__ float g_h[Nn * 128];
__device__ __align__(16) __nv_bfloat16 g_wb[6][2][128 * 136];
__device__ __align__(16) __nv_bfloat16 g_web[2][2][128 * 40];
__device__ int g_tc[4];          // dynamic tile counters (zeroed by prep_all)

// ---------------- helpers -----------------------------------------------------
__device__ __forceinline__ void red_add_v4(float* p, float4 v) {
    asm volatile("red.global.add.v4.f32 [%0], {%1, %2, %3, %4};"
                 :: "l"(p), "f"(v.x), "f"(v.y), "f"(v.z), "f"(v.w)
                 : "memory");
}
__device__ __forceinline__ uint32_t smem_u32(const void* p) {
    return (uint32_t)__cvta_generic_to_shared(p);
}
__device__ __forceinline__ void cp_async16(uint32_t dst, const void* src) {
    asm volatile("cp.async.cg.shared.global [%0], [%1], 16;"
                 :: "r"(dst), "l"(src));
}
__device__ __forceinline__ void cp_commit() {
    asm volatile("cp.async.commit_group;");
}
__device__ __forceinline__ void cp_wait0() {
    asm volatile("cp.async.wait_group 0;" ::: "memory");
}
__device__ __forceinline__ void cp_wait1() {
    asm volatile("cp.async.wait_group 1;" ::: "memory");
}
__device__ __forceinline__ void ldx4(uint32_t* r, uint32_t addr) {
    asm volatile("ldmatrix.sync.aligned.m8n8.x4.shared.b16 {%0, %1, %2, %3}, [%4];"
                 : "=r"(r[0]), "=r"(r[1]), "=r"(r[2]), "=r"(r[3]) : "r"(addr));
}
__device__ __forceinline__ void mma_bf16(float* c, const uint32_t* a,
                                         const uint32_t* b) {
    asm volatile("mma.sync.aligned.m16n8k16.row.col.f32.bf16.bf16.f32 "
                 "{%0, %1, %2, %3}, {%4, %5, %6, %7}, {%8, %9}, {%0, %1, %2, %3};"
                 : "+f"(c[0]), "+f"(c[1]), "+f"(c[2]), "+f"(c[3])
                 : "r"(a[0]), "r"(a[1]), "r"(a[2]), "r"(a[3]),
                   "r"(b[0]), "r"(b[1]));
}
__device__ __forceinline__ uint32_t bf2_u32(__nv_bfloat162 x) {
    uint32_t r;
    memcpy(&r, &x, 4);
    return r;
}
__device__ __forceinline__ uint32_t split_hi2(float a, float b, uint32_t& lo) {
    __nv_bfloat162 h = __floats2bfloat162_rn(a, b);
    __nv_bfloat162 l = __floats2bfloat162_rn(a - __bfloat162float(h.x),
                                             b - __bfloat162float(h.y));
    lo = bf2_u32(l);
    return bf2_u32(h);
}
// ---- bulk copy + mbarrier ----
__device__ __forceinline__ void mbar_init(uint32_t mb, uint32_t cnt) {
    asm volatile("mbarrier.init.shared.b64 [%0], %1;" :: "r"(mb), "r"(cnt) : "memory");
}
__device__ __forceinline__ void mbar_expect(uint32_t mb, uint32_t bytes) {
    asm volatile("mbarrier.arrive.expect_tx.shared.b64 _, [%0], %1;"
                 :: "r"(mb), "r"(bytes) : "memory");
}
__device__ __forceinline__ void bulk_ld(uint32_t dst, const void* src,
                                        uint32_t bytes, uint32_t mb) {
    asm volatile("cp.async.bulk.shared::cta.global.mbarrier::complete_tx::bytes "
                 "[%0], [%1], %2, [%3];"
                 :: "r"(dst), "l"(src), "r"(bytes), "r"(mb) : "memory");
}
__device__ __forceinline__ void mbar_wait(uint32_t mb, uint32_t parity) {
    uint32_t done;
    asm volatile("{\n\t.reg .pred p;\n\t"
                 "mbarrier.try_wait.parity.acquire.cta.shared::cta.b64 p, [%1], %2;\n\t"
                 "selp.b32 %0, 1, 0, p;\n\t}"
                 : "=r"(done) : "r"(mb), "r"(parity) : "memory");
    if (!done) {
        asm volatile("{\n\t.reg .pred P1;\n\t"
                     "WL_%=:\n\t"
                     "mbarrier.try_wait.parity.acquire.cta.shared::cta.b64 P1, [%0], %1, 0x989680;\n\t"
                     "@P1 bra.uni WD_%=;\n\t"
                     "bra.uni WL_%=;\n\t"
                     "WD_%=:\n\t}"
                     :: "r"(mb), "r"(parity) : "memory");
    }
}

// ---------------- fused weight prep + x->agg copy (one launch) -----------------
__global__ void __launch_bounds__(256)
prep_all(const float* __restrict__ W1a, const float* __restrict__ W1b,
         const float* __restrict__ W2a, const float* __restrict__ W2b,
         const float* __restrict__ Wfc1, const float* __restrict__ Wfc2,
         const float* __restrict__ We1, const float* __restrict__ We2,
         __nv_bfloat16* __restrict__ wb, __nv_bfloat16* __restrict__ web,
         int* __restrict__ tc,
         const float4* __restrict__ xsrc, float4* __restrict__ aggdst, int n4) {
    if (blockIdx.x >= 385) {          // copy region: agg = x
        int i = (blockIdx.x - 385) * 256 + threadIdx.x;
        if (i < n4) aggdst[i] = xsrc[i];
        return;
    }
    int id = blockIdx.x * 256 + threadIdx.x;
    if (id < 81920) {
        int m = id / 16384, e = id % 16384;
        const float* W = (m == 0) ? W1a : (m == 1) ? W1b
                       : (m == 2) ? W2a : (m == 3) ? W2b : Wfc1;
        int n = e >> 7, k = e & 127;
        float v = W[k * 128 + n];
        __nv_bfloat16 h = __float2bfloat16_rn(v);
        __nv_bfloat16 l = __float2bfloat16_rn(v - __bfloat162float(h));
        wb[(size_t)m * 2 * 128 * 136 + n * 136 + k] = h;
        wb[((size_t)m * 2 + 1) * 128 * 136 + n * 136 + k] = l;
    } else if (id < 90112) {
        int e = id - 81920;
        int n = e >> 7, k = e & 127;
        float v = Wfc2[k * 64 + n];
        __nv_bfloat16 h = __float2bfloat16_rn(v);
        __nv_bfloat16 l = __float2bfloat16_rn(v - __bfloat162float(h));
        wb[(size_t)5 * 2 * 128 * 136 + n * 136 + k] = h;
        wb[((size_t)5 * 2 + 1) * 128 * 136 + n * 136 + k] = l;
    } else if (id < 98304) {
        int e = id - 90112;
        int m = e >> 12; e &= 4095;
        int n = e >> 5, k = e & 31;
        const float* We = m ? We2 : We1;
        float v = We[k * 128 + n];
        __nv_bfloat16 h = __float2bfloat16_rn(v);
        __nv_bfloat16 l = __float2bfloat16_rn(v - __bfloat162float(h));
        web[(size_t)m * 2 * 128 * 40 + n * 40 + k] = h;
        web[((size_t)m * 2 + 1) * 128 * 40 + n * 40 + k] = l;
    } else if (id < 98308) {
        tc[id - 98304] = 0;
    }
}

// ---------------- persistent HMMA fused edge kernel (32-edge x 64-col warps) ---
// grid=296, 2 CTAs/SM. We/bias resident; ef fp32 + src/dst double-buffered.
// Warp (ew = wid>>1, cz = wid&1): edges [32*ew,+32) x cols [64*cz,+64).
// Halves the per-chunk We ldmatrix traffic vs the 16x128 mapping.
__global__ void __launch_bounds__(256, 2)
edge_kernel(const float* __restrict__ xin,
            const int* __restrict__ src, const int* __restrict__ dst,
            const float* __restrict__ ef,
            const __nv_bfloat16* __restrict__ Weh,
            const __nv_bfloat16* __restrict__ Wel,
            const float* __restrict__ be,
            float* __restrict__ agg, int nchunks) {
    extern __shared__ char sm[];
    const uint32_t s0   = smem_u32(sm);
    const uint32_t sWeh = s0, sWel = s0 + 10240;
    const uint32_t sEfh = s0 + 20480, sEfl = s0 + 30720;
    float* sbias = (float*)(sm + 73728);

    const int tid  = threadIdx.x;
    const int wid  = tid >> 5;
    const int lane = tid & 31;

    auto issue_chunk = [&](int c, int buf) {
        if (c < nchunks) {
            const uint32_t dF = s0 + 40960 + buf * 16384;
            const size_t efmax = (size_t)Ee * 128 - 16;
#pragma unroll
            for (int i = 0; i < 4; i++) {
                int j = tid + i * 256;
                size_t bo = (size_t)c * 16384 + (size_t)j * 16;
                if (bo > efmax) bo = efmax;
                cp_async16(dF + j * 16, (const char*)ef + bo);
            }
            if (tid < 64) {
                const char* sp = (const char*)((tid < 32) ? src : dst);
                int t = tid & 31;
                size_t bo = (size_t)c * 512 + (size_t)t * 16;
                const size_t imax = (size_t)Ee * 4 - 16;
                if (bo > imax) bo = imax;
                cp_async16(s0 + 74240 + buf * 1024 + (tid < 32 ? 0 : 512) + t * 16,
                           sp + bo);
            }
        }
        cp_commit();
    };

    for (int i = tid; i < 640; i += 256) {
        cp_async16(sWeh + i * 16, (const char*)Weh + i * 16);
        cp_async16(sWel + i * 16, (const char*)Wel + i * 16);
    }
    {
        const uint32_t dF = s0 + 40960;
        const size_t efmax = (size_t)Ee * 128 - 16;
        int c = blockIdx.x;
#pragma unroll
        for (int i = 0; i < 4; i++) {
            int j = tid + i * 256;
            size_t bo = (size_t)c * 16384 + (size_t)j * 16;
            if (bo > efmax) bo = efmax;
            cp_async16(dF + j * 16, (const char*)ef + bo);
        }
        if (tid < 64) {
            const char* sp = (const char*)((tid < 32) ? src : dst);
            int t = tid & 31;
            size_t bo = (size_t)c * 512 + (size_t)t * 16;
            const size_t imax = (size_t)Ee * 4 - 16;
            if (bo > imax) bo = imax;
            cp_async16(s0 + 74240 + (tid < 32 ? 0 : 512) + t * 16, sp + bo);
        }
        cp_commit();
        issue_chunk(blockIdx.x + gridDim.x, 1);
    }
    if (tid < 128) sbias[tid] = be[tid];

    const int ew = wid >> 1, cz = wid & 1;
    const int g = lane >> 2, tq = lane & 3;
    const uint32_t aoff0 = sEfh
        + (uint32_t)(ew * 32 + (lane & 15)) * 80 + ((lane >> 4) ? 16 : 0);
    const int brow = (lane & 7) + ((lane >> 4) << 3);
    const uint32_t boff = sWeh + (uint32_t)(cz * 64 + brow) * 80
                        + ((lane & 8) ? 16 : 0);
    const uint32_t bloff = boff + (sWel - sWeh);
    const bool evn = ((lane & 1) == 0);
    const int nk0 = evn ? 0 : 4;
    const int jq  = (lane >> 1) & 1;

    for (int it = 0;; it++) {
        const int c = blockIdx.x + it * gridDim.x;
        if (c >= nchunks) break;
        const int buf = it & 1;
        const int nvalid = min(128, Ee - c * 128);

        cp_wait1();
        __syncthreads();

        // convert staged ef fp32 -> bf16 hi/lo tiles (pitch 40)
        {
            const int edge = tid >> 1, half = tid & 1;
            const float4* fp = (const float4*)(sm + 40960 + buf * 16384
                                               + edge * 128 + half * 64);
            const uint32_t dh = sEfh + edge * 80 + half * 32;
            const uint32_t dl = sEfl + edge * 80 + half * 32;
#pragma unroll
            for (int i = 0; i < 4; i++) {
                float4 v = fp[i];
                uint32_t l0, l1;
                uint32_t h0 = split_hi2(v.x, v.y, l0);
                uint32_t h1 = split_hi2(v.z, v.w, l1);
                asm volatile("st.shared.v2.b32 [%0], {%1, %2};"
                             :: "r"(dh + i * 8), "r"(h0), "r"(h1));
                asm volatile("st.shared.v2.b32 [%0], {%1, %2};"
                             :: "r"(dl + i * 8), "r"(l0), "r"(l1));
            }
        }
        // src/dst to registers (4 edge rows per thread: 2 mi x 2 half)
        const int* ib = (const int*)(sm + 74240 + buf * 1024);
        int sR[2][2], dR[2][2];
#pragma unroll
        for (int mi = 0; mi < 2; mi++)
#pragma unroll
            for (int half = 0; half < 2; half++) {
                const int er = ew * 32 + mi * 16 + half * 8 + g;
                sR[mi][half] = ib[er];
                dR[mi][half] = ib[128 + er];
            }
        __syncthreads();

        // MMA: warp computes 32 edges x 64 cols (bias-seeded)
        float acc[2][8][4];
#pragma unroll
        for (int ni = 0; ni < 8; ni++) {
            float2 b = *(const float2*)(sbias + cz * 64 + ni * 8 + tq * 2);
#pragma unroll
            for (int mi = 0; mi < 2; mi++) {
                acc[mi][ni][0] = b.x; acc[mi][ni][1] = b.y;
                acc[mi][ni][2] = b.x; acc[mi][ni][3] = b.y;
            }
        }
#pragma unroll
        for (int ks = 0; ks < 2; ks++) {
            uint32_t ah[2][4], al[2][4];
#pragma unroll
            for (int mi = 0; mi < 2; mi++) {
                ldx4(ah[mi], aoff0 + mi * (16 * 80) + ks * 32);
                ldx4(al[mi], aoff0 + (sEfl - sEfh) + mi * (16 * 80) + ks * 32);
            }
#pragma unroll
            for (int np = 0; np < 4; np++) {
                uint32_t rh[4], rl[4];
                ldx4(rh, boff + np * (16 * 80) + ks * 32);
                ldx4(rl, bloff + np * (16 * 80) + ks * 32);
                uint32_t bh0[2] = {rh[0], rh[1]}, bh1[2] = {rh[2], rh[3]};
                uint32_t bl0[2] = {rl[0], rl[1]}, bl1[2] = {rl[2], rl[3]};
#pragma unroll
                for (int mi = 0; mi < 2; mi++) {
                    mma_bf16(acc[mi][np * 2],     ah[mi], bh0);
                    mma_bf16(acc[mi][np * 2],     ah[mi], bl0);
                    mma_bf16(acc[mi][np * 2],     al[mi], bh0);
                    mma_bf16(acc[mi][np * 2 + 1], ah[mi], bh1);
                    mma_bf16(acc[mi][np * 2 + 1], ah[mi], bl1);
                    mma_bf16(acc[mi][np * 2 + 1], al[mi], bh1);
                }
            }
        }
        __syncthreads();       // tile reads done -> safe to restage buf

        issue_chunk(c + 2 * gridDim.x, buf);

        // lane-pair merge -> float4 ownership (even lanes ni 0..3, odd 4..7)
        float4 rowA[2][4], rowB[2][4];
#pragma unroll
        for (int mi = 0; mi < 2; mi++)
#pragma unroll
            for (int i = 0; i < 4; i++) {
                float s0v = evn ? acc[mi][i + 4][0] : acc[mi][i][0];
                float s1v = evn ? acc[mi][i + 4][1] : acc[mi][i][1];
                float s2v = evn ? acc[mi][i + 4][2] : acc[mi][i][2];
                float s3v = evn ? acc[mi][i + 4][3] : acc[mi][i][3];
                float g0 = __shfl_xor_sync(0xffffffffu, s0v, 1);
                float g1 = __shfl_xor_sync(0xffffffffu, s1v, 1);
                float g2 = __shfl_xor_sync(0xffffffffu, s2v, 1);
                float g3 = __shfl_xor_sync(0xffffffffu, s3v, 1);
                float k0 = evn ? acc[mi][i][0] : acc[mi][i + 4][0];
                float k1 = evn ? acc[mi][i][1] : acc[mi][i + 4][1];
                float k2 = evn ? acc[mi][i][2] : acc[mi][i + 4][2];
                float k3 = evn ? acc[mi][i][3] : acc[mi][i + 4][3];
                rowA[mi][i] = evn ? make_float4(k0, k1, g0, g1)
                                  : make_float4(g0, g1, k0, k1);
                rowB[mi][i] = evn ? make_float4(k2, k3, g2, g3)
                                  : make_float4(g2, g3, k2, k3);
            }

        // register epilogue: batched gathers + red.add.v4
#pragma unroll
        for (int mi = 0; mi < 2; mi++)
#pragma unroll
            for (int half = 0; half < 2; half++) {
                const int er = ew * 32 + mi * 16 + half * 8 + g;
                if (er < nvalid) {
                    const size_t srow = (size_t)sR[mi][half] * 128;
                    const size_t drow = (size_t)dR[mi][half] * 128;
#pragma unroll
                    for (int i = 0; i < 4; i++) {
                        const int cb = cz * 64 + (nk0 + i) * 8 + 4 * jq;
                        float4 ev = half ? rowB[mi][i] : rowA[mi][i];
                        float4 xv = *(const float4*)(xin + srow + cb);
                        float4 m;
                        m.x = fmaxf(xv.x + ev.x, 0.f);
                        m.y = fmaxf(xv.y + ev.y, 0.f);
                        m.z = fmaxf(xv.z + ev.z, 0.f);
                        m.w = fmaxf(xv.w + ev.w, 0.f);
                        red_add_v4(agg + drow + cb, m);
                    }
                }
            }
    }
    cp_wait0();
}

// ---------------- shared GEMM pieces -------------------------------------------
template <int NF>
__device__ __forceinline__ void mma_stage(
    uint32_t sAh, uint32_t sAl, uint32_t sWh, uint32_t sWl,
    uint32_t aoff, int cw, int lane, const float* __restrict__ bias,
    float (&acc)[4][NF][4]) {
    const int tq = lane & 3;
    const int brow = (lane & 7) + ((lane >> 4) << 3);
    const uint32_t boff = (uint32_t)(cw * (8 * NF) + brow) * 272
                        + ((lane & 8) ? 16 : 0);
#pragma unroll
    for (int ni = 0; ni < NF; ni++) {
        float2 b = __ldg((const float2*)(bias + cw * (8 * NF) + ni * 8 + tq * 2));
#pragma unroll
        for (int mi = 0; mi < 4; mi++) {
            acc[mi][ni][0] = b.x; acc[mi][ni][1] = b.y;
            acc[mi][ni][2] = b.x; acc[mi][ni][3] = b.y;
        }
    }
#pragma unroll
    for (int ks = 0; ks < 8; ks++) {
        uint32_t ah[4][4], al[4][4], bh[NF][2], bl[NF][2];
#pragma unroll
        for (int mi = 0; mi < 4; mi++) {
            ldx4(ah[mi], sAh + aoff + mi * 4352 + ks * 32);
            ldx4(al[mi], sAl + aoff + mi * 4352 + ks * 32);
        }
#pragma unroll
        for (int np = 0; np < NF / 2; np++) {
            uint32_t r[4];
            ldx4(r, sWh + boff + np * 4352 + ks * 32);
            bh[np * 2][0] = r[0]; bh[np * 2][1] = r[1];
            bh[np * 2 + 1][0] = r[2]; bh[np * 2 + 1][1] = r[3];
            ldx4(r, sWl + boff + np * 4352 + ks * 32);
            bl[np * 2][0] = r[0]; bl[np * 2][1] = r[1];
            bl[np * 2 + 1][0] = r[2]; bl[np * 2 + 1][1] = r[3];
        }
#pragma unroll
        for (int mi = 0; mi < 4; mi++)
#pragma unroll
            for (int ni = 0; ni < NF; ni++) {
                mma_bf16(acc[mi][ni], ah[mi], bh[ni]);
                mma_bf16(acc[mi][ni], ah[mi], bl[ni]);
                mma_bf16(acc[mi][ni], al[mi], bh[ni]);
            }
    }
}

template <int ACT>
__device__ __forceinline__ void twrite(
    float (&acc)[4][4][4], uint32_t sAh, uint32_t sAl, int cw, int lane) {
    const int g = lane >> 2, tq = lane & 3;
#pragma unroll
    for (int mi = 0; mi < 4; mi++) {
        const int r0 = mi * 16 + g;
#pragma unroll
        for (int ni = 0; ni < 4; ni++) {
            const int col = cw * 32 + ni * 8 + tq * 2;
            float v0 = acc[mi][ni][0], v1 = acc[mi][ni][1];
            float v2 = acc[mi][ni][2], v3 = acc[mi][ni][3];
            if (ACT == 1) {
                v0 = fmaxf(v0, 0.f); v1 = fmaxf(v1, 0.f);
                v2 = fmaxf(v2, 0.f); v3 = fmaxf(v3, 0.f);
            } else {
                v0 = tanhf(v0); v1 = tanhf(v1);
                v2 = tanhf(v2); v3 = tanhf(v3);
            }
            uint32_t lo0, lo1;
            uint32_t hi0 = split_hi2(v0, v1, lo0);
            uint32_t hi1 = split_hi2(v2, v3, lo1);
            const uint32_t d0 = (uint32_t)r0 * 272 + col * 2;
            asm volatile("st.shared.b32 [%0], %1;" :: "r"(sAh + d0), "r"(hi0));
            asm volatile("st.shared.b32 [%0], %1;" :: "r"(sAl + d0), "r"(lo0));
            asm volatile("st.shared.b32 [%0], %1;" :: "r"(sAh + d0 + 8 * 272), "r"(hi1));
            asm volatile("st.shared.b32 [%0], %1;" :: "r"(sAl + d0 + 8 * 272), "r"(lo1));
        }
    }
}

__device__ __forceinline__ void aconvert(
    const float* __restrict__ A, int mbase, int nrows,
    uint32_t sAh, uint32_t sAl, int tid) {
    const int row = tid >> 1, half = tid & 1;
    int grow = min(mbase + row, nrows - 1);
    const float* ap = A + (size_t)grow * 128 + half * 64;
    const uint32_t d = row * 272 + half * 128;
#pragma unroll
    for (int i = 0; i < 8; i++) {
        float4 v0 = *(const float4*)(ap + i * 8);
        float4 v1 = *(const float4*)(ap + i * 8 + 4);
        uint32_t l0, l1, l2, l3;
        uint32_t h0 = split_hi2(v0.x, v0.y, l0);
        uint32_t h1 = split_hi2(v0.z, v0.w, l1);
        uint32_t h2 = split_hi2(v1.x, v1.y, l2);
        uint32_t h3 = split_hi2(v1.z, v1.w, l3);
        asm volatile("st.shared.v4.b32 [%0], {%1, %2, %3, %4};"
                     :: "r"(sAh + d + i * 16), "r"(h0), "r"(h1), "r"(h2), "r"(h3));
        asm volatile("st.shared.v4.b32 [%0], {%1, %2, %3, %4};"
                     :: "r"(sAl + d + i * 16), "r"(l0), "r"(l1), "r"(l2), "r"(l3));
    }
}

// issue half-split W load: half0 -> mb0 (warps 0-1), half1 -> mb1 (warps 2-3)
__device__ __forceinline__ void loadW_split(
    const __nv_bfloat16* Wp, uint32_t sWh, uint32_t sWl,
    uint32_t mb0, uint32_t mb1, int tid) {
    const char* p = (const char*)Wp;
    if (tid == 0) {
        mbar_expect(mb0, 34816);
        bulk_ld(sWh, p, 17408, mb0);
        bulk_ld(sWl, p + 34816, 17408, mb0);
    }
    if (tid == 32) {
        mbar_expect(mb1, 34816);
        bulk_ld(sWh + 17408, p + 17408, 17408, mb1);
        bulk_ld(sWl + 17408, p + 34816 + 17408, 17408, mb1);
    }
}

// ---------------- two-stage fused node GEMM (dyn sched + W half-split) ---------
template <int COUT2, int ACT1, int ACT2>
__global__ void __launch_bounds__(128, 2)
fgemm(const float* __restrict__ A,
      const __nv_bfloat16* __restrict__ W1, const __nv_bfloat16* __restrict__ W2,
      const float* __restrict__ b1, const float* __restrict__ b2,
      float* __restrict__ out, float* __restrict__ out2, int nrows, int ntiles,
      int* __restrict__ tc) {
    constexpr int NW2 = COUT2 / 4;
    constexpr int NF2 = NW2 / 8;
    constexpr uint32_t AB  = 64 * 272;
    constexpr uint32_t WHB = 128 * 272;

    extern __shared__ char sm[];
    const uint32_t s0  = smem_u32(sm);
    const uint32_t sAh = s0, sAl = s0 + AB;
    const uint32_t sWh = s0 + 2 * AB, sWl = sWh + WHB;
    __shared__ __align__(8) unsigned long long bw_store[2];
    __shared__ int s_mt;
    const uint32_t bw0 = smem_u32(&bw_store[0]);
    const uint32_t bw1 = smem_u32(&bw_store[1]);

    const int tid  = threadIdx.x;
    const int lane = tid & 31;
    const int cw   = tid >> 5;
    const int g = lane >> 2, tq = lane & 3;
    const uint32_t aoff = (uint32_t)(lane & 15) * 272 + ((lane >> 4) ? 16 : 0);
    const uint32_t mybar128 = (cw < 2) ? bw0 : bw1;
    const uint32_t mybarL   = (COUT2 == 128) ? mybar128 : bw0;

    if (tid == 0) { mbar_init(bw0, 1); mbar_init(bw1, 1); }
    __syncthreads();
    loadW_split(W1, sWh, sWl, bw0, bw1, tid);

    int ph = 0;
    for (;;) {
        if (tid == 0) s_mt = atomicAdd(tc, 1);
        __syncthreads();
        const int mt = s_mt;
        if (mt >= ntiles) break;
        const int mbase = mt * 64;

        aconvert(A, mbase, nrows, sAh, sAl, tid);
        __syncthreads();
        mbar_wait(mybar128, ph & 1); ph++;

        float acc[4][4][4];
        mma_stage<4>(sAh, sAl, sWh, sWl, aoff, cw, lane, b1, acc);
        __syncthreads();
        loadW_split(W2, sWh, sWl, bw0, bw1, tid);
        twrite<ACT1>(acc, sAh, sAl, cw, lane);
        __syncthreads();
        mbar_wait(mybarL, ph & 1); ph++;

        float acc2[4][NF2][4];
        mma_stage<NF2>(sAh, sAl, sWh, sWl, aoff, cw, lane, b2, acc2);
        __syncthreads();
        loadW_split(W1, sWh, sWl, bw0, bw1, tid);
#pragma unroll
        for (int mi = 0; mi < 4; mi++) {
            const int r0 = mbase + mi * 16 + g;
#pragma unroll
            for (int ni = 0; ni < NF2; ni++) {
                const int col = cw * NW2 + ni * 8 + tq * 2;
                float v0 = acc2[mi][ni][0], v1 = acc2[mi][ni][1];
                float v2 = acc2[mi][ni][2], v3 = acc2[mi][ni][3];
                if (ACT2 == 2) {
                    v0 = tanhf(v0); v1 = tanhf(v1);
                    v2 = tanhf(v2); v3 = tanhf(v3);
                }
                if (r0 < nrows) {
                    *(float2*)(out + (size_t)r0 * COUT2 + col) = make_float2(v0, v1);
                    if (out2)
                        *(float2*)(out2 + (size_t)r0 * COUT2 + col) = make_float2(v0, v1);
                }
                if (r0 + 8 < nrows) {
                    *(float2*)(out + (size_t)(r0 + 8) * COUT2 + col) = make_float2(v2, v3);
                    if (out2)
                        *(float2*)(out2 + (size_t)(r0 + 8) * COUT2 + col) = make_float2(v2, v3);
                }
            }
        }
    }
    mbar_wait(bw0, ph & 1);
    mbar_wait(bw1, ph & 1);
}

// ---------------- four-stage fused GEMM (dyn sched + W half-split) -------------
__global__ void __launch_bounds__(128, 2)
fgemm4(const float* __restrict__ A,
       const __nv_bfloat16* __restrict__ Wa, const __nv_bfloat16* __restrict__ Wb,
       const __nv_bfloat16* __restrict__ Wc, const __nv_bfloat16* __restrict__ Wd,
       const float* __restrict__ ba, const float* __restrict__ bb,
       const float* __restrict__ bc, const float* __restrict__ bd,
       float* __restrict__ out, int nrows, int ntiles, int* __restrict__ tc) {
    constexpr uint32_t AB  = 64 * 272;
    constexpr uint32_t WHB = 128 * 272;

    extern __shared__ char sm[];
    const uint32_t s0  = smem_u32(sm);
    const uint32_t sAh = s0, sAl = s0 + AB;
    const uint32_t sWh = s0 + 2 * AB, sWl = sWh + WHB;
    __shared__ __align__(8) unsigned long long bw_store[2];
    __shared__ int s_mt;
    const uint32_t bw0 = smem_u32(&bw_store[0]);
    const uint32_t bw1 = smem_u32(&bw_store[1]);

    const int tid  = threadIdx.x;
    const int lane = tid & 31;
    const int cw   = tid >> 5;
    const int g = lane >> 2, tq = lane & 3;
    const uint32_t aoff = (uint32_t)(lane & 15) * 272 + ((lane >> 4) ? 16 : 0);
    const uint32_t mybar128 = (cw < 2) ? bw0 : bw1;

    if (tid == 0) { mbar_init(bw0, 1); mbar_init(bw1, 1); }
    __syncthreads();
    loadW_split(Wa, sWh, sWl, bw0, bw1, tid);

    int ph = 0;
    for (;;) {
        if (tid == 0) s_mt = atomicAdd(tc, 1);
        __syncthreads();
        const int mt = s_mt;
        if (mt >= ntiles) break;
        const int mbase = mt * 64;

        aconvert(A, mbase, nrows, sAh, sAl, tid);
        __syncthreads();
        mbar_wait(mybar128, ph & 1); ph++;

        {   // stage 1: relu(A@Wa+ba)
            float acc[4][4][4];
            mma_stage<4>(sAh, sAl, sWh, sWl, aoff, cw, lane, ba, acc);
            __syncthreads();
            loadW_split(Wb, sWh, sWl, bw0, bw1, tid);
            twrite<1>(acc, sAh, sAl, cw, lane);
            __syncthreads();
            mbar_wait(mybar128, ph & 1); ph++;
        }
        {   // stage 2: tanh(T@Wb+bb)
            float acc[4][4][4];
            mma_stage<4>(sAh, sAl, sWh, sWl, aoff, cw, lane, bb, acc);
            __syncthreads();
            loadW_split(Wc, sWh, sWl, bw0, bw1, tid);
            twrite<2>(acc, sAh, sAl, cw, lane);
            __syncthreads();
            mbar_wait(mybar128, ph & 1); ph++;
        }
        {   // stage 3: tanh(T@Wc+bc)
            float acc[4][4][4];
            mma_stage<4>(sAh, sAl, sWh, sWl, aoff, cw, lane, bc, acc);
            __syncthreads();
            loadW_split(Wd, sWh, sWl, bw0, bw1, tid);
            twrite<2>(acc, sAh, sAl, cw, lane);
            __syncthreads();
            mbar_wait(bw0, ph & 1); ph++;    // COUT 64: all warps read half0
        }
        {   // stage 4: T@Wd+bd -> out (COUT 64)
            float acc[4][2][4];
            mma_stage<2>(sAh, sAl, sWh, sWl, aoff, cw, lane, bd, acc);
            __syncthreads();
            loadW_split(Wa, sWh, sWl, bw0, bw1, tid);
#pragma unroll
            for (int mi = 0; mi < 4; mi++) {
                const int r0 = mbase + mi * 16 + g;
#pragma unroll
                for (int ni = 0; ni < 2; ni++) {
                    const int col = cw * 16 + ni * 8 + tq * 2;
                    if (r0 < nrows)
                        *(float2*)(out + (size_t)r0 * 64 + col)
                            = make_float2(acc[mi][ni][0], acc[mi][ni][1]);
                    if (r0 + 8 < nrows)
                        *(float2*)(out + (size_t)(r0 + 8) * 64 + col)
                            = make_float2(acc[mi][ni][2], acc[mi][ni][3]);
                }
            }
        }
    }
    mbar_wait(bw0, ph & 1);
    mbar_wait(bw1, ph & 1);
}

// ---------------- launch ------------------------------------------------------
extern "C" void kernel_launch(void* const* d_in, const int* in_sizes, int n_in,
                              void* d_out, int out_size) {
    const float* x    = (const float*)d_in[0];
    const int*   ei   = (const int*)d_in[1];
    const float* ef   = (const float*)d_in[2];
    const float* We1  = (const float*)d_in[3];
    const float* be1  = (const float*)d_in[4];
    const float* W1a  = (const float*)d_in[5];
    const float* b1a  = (const float*)d_in[6];
    const float* W1b  = (const float*)d_in[7];
    const float* b1b  = (const float*)d_in[8];
    const float* We2  = (const float*)d_in[9];
    const float* be2  = (const float*)d_in[10];
    const float* W2a  = (const float*)d_in[11];
    const float* b2a  = (const float*)d_in[12];
    const float* W2b  = (const float*)d_in[13];
    const float* b2b  = (const float*)d_in[14];
    const float* Wfc1 = (const float*)d_in[15];
    const float* bfc1 = (const float*)d_in[16];
    const float* Wfc2 = (const float*)d_in[17];
    const float* bfc2 = (const float*)d_in[18];
    float* out = (float*)d_out;

    float *agg, *h;
    __nv_bfloat16 *wb, *web;
    int* tc;
    cudaGetSymbolAddress((void**)&agg, g_agg);
    cudaGetSymbolAddress((void**)&h,   g_h);
    cudaGetSymbolAddress((void**)&wb,  g_wb);
    cudaGetSymbolAddress((void**)&web, g_web);
    cudaGetSymbolAddress((void**)&tc,  g_tc);
    auto WB = [&](int m) { return wb + (size_t)m * 2 * 128 * 136; };
    auto WE = [&](int m, int s) { return web + ((size_t)m * 2 + s) * 128 * 40; };

    const int* srcp = ei;
    const int* dstp = ei + Ee;

    const int n4 = Nn * 128 / 4;
    const int prepG = 385 + (n4 + 255) / 256;
    const int nchunks = (Ee + 127) / 128;        // 4688
    const int ntiles = (Nn + 63) / 64;           // 1563
    const int gG = 296;

    constexpr int SME = 76288;
    constexpr int SMF = 2 * 17408 + 2 * 34816;   // 104448
    cudaFuncSetAttribute(edge_kernel, cudaFuncAttributeMaxDynamicSharedMemorySize, SME);
    cudaFuncSetAttribute(fgemm<128, 1, 2>, cudaFuncAttributeMaxDynamicSharedMemorySize, SMF);
    cudaFuncSetAttribute(fgemm4, cudaFuncAttributeMaxDynamicSharedMemorySize, SMF);

    prep_all<<<prepG, 256>>>(W1a, W1b, W2a, W2b, Wfc1, Wfc2, We1, We2, wb, web, tc,
                             (const float4*)x, (float4*)agg, n4);

    // Layer 1: agg(=x) += relu-msgs; h = tanh(relu(agg@W1a)@W1b); agg = h
    edge_kernel<<<gG, 256, SME>>>(x, srcp, dstp, ef, WE(0, 0), WE(0, 1), be1,
                                  agg, nchunks);
    fgemm<128, 1, 2><<<gG, 128, SMF>>>(agg, WB(0), WB(1), b1a, b1b, h, agg,
                                       Nn, ntiles, tc + 0);

    // Layer 2 + head (fused): agg(=h) += msgs(h);
    // out = tanh(tanh(relu(agg@W2a)@W2b)@Wfc1)@Wfc2
    edge_kernel<<<gG, 256, SME>>>(h, srcp, dstp, ef, WE(1, 0), WE(1, 1), be2,
                                  agg, nchunks);
    fgemm4<<<gG, 128, SMF>>>(agg, WB(2), WB(3), WB(4), WB(5),
                             b2a, b2b, bfc1, bfc2, out, Nn, ntiles, tc + 1);
}